// round 1
// baseline (speedup 1.0000x reference)
#include <cuda_runtime.h>
#include <math.h>

#define NHEADS 16
#define BATCH  2
#define SEQ    2048
#define DMODEL 1024
#define HID    64
#define MROWS  (BATCH*SEQ)   // 4096
#define NORM   0.125f        // 1/sqrt(64)

// Scratch (device globals: no allocation allowed in kernel_launch)
__device__ float g_Q[NHEADS*BATCH*SEQ*HID];   // [h][b][s][e]
__device__ float g_K[NHEADS*BATCH*SEQ*HID];
__device__ float g_V[NHEADS*BATCH*SEQ*HID];
__device__ float g_Hd[BATCH*SEQ*DMODEL];      // [b][s][h*64+e]

// ---------------------------------------------------------------------------
// Projection GEMM: C[m][n] = sum_k X[m][k] * W[h][k][e], n = h*64+e
// X: [4096,1024] row-major. W: [16,1024,64] row-major.
// Output scattered into g_Q/g_K/g_V in [h][b][s][e] layout.
// Tile: BM=128, BN=64, BK=16; 256 threads; 8x4 per-thread microtile.
// ---------------------------------------------------------------------------
__global__ void gemm_proj_kernel(const float* __restrict__ X,
                                 const float* __restrict__ W,
                                 int which)
{
    const int K = DMODEL;
    __shared__ __align__(16) float As[16][129];  // [k][m], padded
    __shared__ __align__(16) float Bs[16][64];   // [k][e]

    const int tid = threadIdx.x;
    const int tx = tid & 15, ty = tid >> 4;
    const int n0 = blockIdx.x * 64;
    const int m0 = blockIdx.y * 128;
    const int h  = n0 >> 6;                      // BN==64 -> one head per block col
    const float* Wp = W + (size_t)h * K * HID;

    float acc[8][4];
    #pragma unroll
    for (int i = 0; i < 8; i++)
        #pragma unroll
        for (int j = 0; j < 4; j++) acc[i][j] = 0.f;

    for (int k0 = 0; k0 < K; k0 += 16) {
        // A tile: 128x16 -> 512 float4, 2 per thread, stored transposed
        #pragma unroll
        for (int t = 0; t < 2; t++) {
            int f   = tid + t * 256;
            int row = f >> 2;
            int kq  = (f & 3) * 4;
            float4 a4 = *(const float4*)(X + (size_t)(m0 + row) * K + k0 + kq);
            As[kq + 0][row] = a4.x; As[kq + 1][row] = a4.y;
            As[kq + 2][row] = a4.z; As[kq + 3][row] = a4.w;
        }
        // B tile: 16x64 -> 256 float4, 1 per thread
        {
            int kk = tid >> 4;
            int e4 = (tid & 15) * 4;
            float4 b4 = *(const float4*)(Wp + (size_t)(k0 + kk) * HID + e4);
            *(float4*)&Bs[kk][e4] = b4;
        }
        __syncthreads();
        #pragma unroll
        for (int kk = 0; kk < 16; kk++) {
            float4 b = *(float4*)&Bs[kk][tx * 4];
            float a[8];
            #pragma unroll
            for (int i = 0; i < 8; i++) a[i] = As[kk][ty * 8 + i];
            #pragma unroll
            for (int i = 0; i < 8; i++) {
                acc[i][0] += a[i] * b.x; acc[i][1] += a[i] * b.y;
                acc[i][2] += a[i] * b.z; acc[i][3] += a[i] * b.w;
            }
        }
        __syncthreads();
    }

    float* Out = (which == 0) ? g_Q : (which == 1) ? g_K : g_V;
    #pragma unroll
    for (int i = 0; i < 8; i++) {
        int m  = m0 + ty * 8 + i;
        int b_ = m / SEQ, s_ = m % SEQ;
        float* orow = Out + (((size_t)h * BATCH + b_) * SEQ + s_) * HID;
        #pragma unroll
        for (int j = 0; j < 4; j++) orow[tx * 4 + j] = acc[i][j];
    }
}

// ---------------------------------------------------------------------------
// Output projection: out[m][n] = sum_k g_Hd[m][k] * Wo[k][n]
// Wo flattened (h,e,o) -> [1024,1024] row-major matches k = h*64+e.
// ---------------------------------------------------------------------------
__global__ void gemm_out_kernel(const float* __restrict__ W,
                                float* __restrict__ Out)
{
    const int K = DMODEL, N = DMODEL;
    __shared__ __align__(16) float As[16][129];
    __shared__ __align__(16) float Bs[16][64];

    const int tid = threadIdx.x;
    const int tx = tid & 15, ty = tid >> 4;
    const int n0 = blockIdx.x * 64;
    const int m0 = blockIdx.y * 128;

    float acc[8][4];
    #pragma unroll
    for (int i = 0; i < 8; i++)
        #pragma unroll
        for (int j = 0; j < 4; j++) acc[i][j] = 0.f;

    for (int k0 = 0; k0 < K; k0 += 16) {
        #pragma unroll
        for (int t = 0; t < 2; t++) {
            int f   = tid + t * 256;
            int row = f >> 2;
            int kq  = (f & 3) * 4;
            float4 a4 = *(const float4*)(g_Hd + (size_t)(m0 + row) * K + k0 + kq);
            As[kq + 0][row] = a4.x; As[kq + 1][row] = a4.y;
            As[kq + 2][row] = a4.z; As[kq + 3][row] = a4.w;
        }
        {
            int kk = tid >> 4;
            int e4 = (tid & 15) * 4;
            float4 b4 = *(const float4*)(W + (size_t)(k0 + kk) * N + n0 + e4);
            *(float4*)&Bs[kk][e4] = b4;
        }
        __syncthreads();
        #pragma unroll
        for (int kk = 0; kk < 16; kk++) {
            float4 b = *(float4*)&Bs[kk][tx * 4];
            float a[8];
            #pragma unroll
            for (int i = 0; i < 8; i++) a[i] = As[kk][ty * 8 + i];
            #pragma unroll
            for (int i = 0; i < 8; i++) {
                acc[i][0] += a[i] * b.x; acc[i][1] += a[i] * b.y;
                acc[i][2] += a[i] * b.z; acc[i][3] += a[i] * b.w;
            }
        }
        __syncthreads();
    }

    #pragma unroll
    for (int i = 0; i < 8; i++) {
        int m = m0 + ty * 8 + i;
        #pragma unroll
        for (int j = 0; j < 4; j++)
            Out[(size_t)m * N + n0 + tx * 4 + j] = acc[i][j];
    }
}

// ---------------------------------------------------------------------------
// Flash attention, fp32. One block per (q-tile=64, head, batch).
// 256 threads; thread (ty,tx) owns 4 q-rows x 4 cols.
// Smem: Qs[64][64] + KVs[64][64] (K transposed, then V) + Ss[64][64] = 48KB.
// ---------------------------------------------------------------------------
__global__ void attn_kernel()
{
    __shared__ __align__(16) float Qs[64][64];   // [q][e], pre-scaled by NORM
    __shared__ __align__(16) float KVs[64][64];  // phase 1: [e][k] ; phase 2: [k][e]
    __shared__ __align__(16) float Ss[64][64];   // P tile [q][k]

    const int tid = threadIdx.x;
    const int tx = tid & 15, ty = tid >> 4;
    const int q0 = blockIdx.x * 64;
    const int h  = blockIdx.y;
    const int b  = blockIdx.z;

    const size_t base = ((size_t)h * BATCH + b) * SEQ * HID;
    const float* Qg = g_Q + base;
    const float* Kg = g_K + base;
    const float* Vg = g_V + base;

    // Load Q tile (scaled by NORM): 1024 float4, 4 per thread
    #pragma unroll
    for (int t = 0; t < 4; t++) {
        int f   = tid + t * 256;
        int row = f >> 4;
        int c4  = (f & 15) * 4;
        float4 a4 = *(const float4*)(Qg + (size_t)(q0 + row) * HID + c4);
        Qs[row][c4 + 0] = a4.x * NORM; Qs[row][c4 + 1] = a4.y * NORM;
        Qs[row][c4 + 2] = a4.z * NORM; Qs[row][c4 + 3] = a4.w * NORM;
    }

    float m_i[4], l_i[4], acc[4][4];
    #pragma unroll
    for (int i = 0; i < 4; i++) {
        m_i[i] = -1e30f; l_i[i] = 0.f;
        #pragma unroll
        for (int j = 0; j < 4; j++) acc[i][j] = 0.f;
    }
    __syncthreads();

    for (int kt = 0; kt < SEQ / 64; kt++) {
        const int k0 = kt * 64;
        // Load K tile TRANSPOSED: KVs[e][k] = K[k0+k][e]
        #pragma unroll
        for (int t = 0; t < 4; t++) {
            int f  = tid + t * 256;
            int kk = f >> 4;
            int e4 = (f & 15) * 4;
            float4 a4 = *(const float4*)(Kg + (size_t)(k0 + kk) * HID + e4);
            KVs[e4 + 0][kk] = a4.x; KVs[e4 + 1][kk] = a4.y;
            KVs[e4 + 2][kk] = a4.z; KVs[e4 + 3][kk] = a4.w;
        }
        __syncthreads();

        // S = Q K^T (scaled), 4x4 per thread
        float s[4][4];
        #pragma unroll
        for (int i = 0; i < 4; i++)
            #pragma unroll
            for (int j = 0; j < 4; j++) s[i][j] = 0.f;
        #pragma unroll 8
        for (int e = 0; e < 64; e++) {
            float a[4], bb[4];
            #pragma unroll
            for (int i = 0; i < 4; i++) a[i]  = Qs[ty * 4 + i][e];
            #pragma unroll
            for (int j = 0; j < 4; j++) bb[j] = KVs[e][tx * 4 + j];
            #pragma unroll
            for (int i = 0; i < 4; i++)
                #pragma unroll
                for (int j = 0; j < 4; j++) s[i][j] += a[i] * bb[j];
        }
        __syncthreads();  // done reading K before V overwrites KVs

        // Online softmax: row groups are the 16 tx-lanes (xor 1,2,4,8 stays in group)
        #pragma unroll
        for (int i = 0; i < 4; i++) {
            float mt = s[i][0];
            #pragma unroll
            for (int j = 1; j < 4; j++) mt = fmaxf(mt, s[i][j]);
            #pragma unroll
            for (int off = 8; off >= 1; off >>= 1)
                mt = fmaxf(mt, __shfl_xor_sync(0xffffffffu, mt, off));
            float mn    = fmaxf(m_i[i], mt);
            float alpha = __expf(m_i[i] - mn);
            float lt = 0.f;
            #pragma unroll
            for (int j = 0; j < 4; j++) {
                float p = __expf(s[i][j] - mn);
                s[i][j] = p; lt += p;
            }
            #pragma unroll
            for (int off = 8; off >= 1; off >>= 1)
                lt += __shfl_xor_sync(0xffffffffu, lt, off);
            l_i[i] = l_i[i] * alpha + lt;
            m_i[i] = mn;
            #pragma unroll
            for (int j = 0; j < 4; j++) acc[i][j] *= alpha;
        }

        // Store P; load V into KVs[k][e]
        #pragma unroll
        for (int i = 0; i < 4; i++)
            #pragma unroll
            for (int j = 0; j < 4; j++)
                Ss[ty * 4 + i][tx * 4 + j] = s[i][j];
        #pragma unroll
        for (int t = 0; t < 4; t++) {
            int f  = tid + t * 256;
            int kk = f >> 4;
            int e4 = (f & 15) * 4;
            *(float4*)&KVs[kk][e4] =
                *(const float4*)(Vg + (size_t)(k0 + kk) * HID + e4);
        }
        __syncthreads();

        // O += P V
        #pragma unroll 8
        for (int kk = 0; kk < 64; kk++) {
            float4 vv = *(float4*)&KVs[kk][tx * 4];
            float p[4];
            #pragma unroll
            for (int i = 0; i < 4; i++) p[i] = Ss[ty * 4 + i][kk];
            #pragma unroll
            for (int i = 0; i < 4; i++) {
                acc[i][0] += p[i] * vv.x; acc[i][1] += p[i] * vv.y;
                acc[i][2] += p[i] * vv.z; acc[i][3] += p[i] * vv.w;
            }
        }
        __syncthreads();  // done reading V before next K overwrites KVs
    }

    // Normalize and write heads: [b][q][h*64+e]
    #pragma unroll
    for (int i = 0; i < 4; i++) {
        int q = q0 + ty * 4 + i;
        float inv = 1.f / l_i[i];
        float* orow = g_Hd + ((size_t)b * SEQ + q) * DMODEL + h * HID;
        #pragma unroll
        for (int j = 0; j < 4; j++) orow[tx * 4 + j] = acc[i][j] * inv;
    }
}

// ---------------------------------------------------------------------------
extern "C" void kernel_launch(void* const* d_in, const int* in_sizes, int n_in,
                              void* d_out, int out_size)
{
    const float* q  = (const float*)d_in[0];
    const float* k  = (const float*)d_in[1];
    const float* v  = (const float*)d_in[2];
    const float* Wq = (const float*)d_in[3];
    const float* Wk = (const float*)d_in[4];
    const float* Wv = (const float*)d_in[5];
    const float* Wo = (const float*)d_in[6];
    float* out = (float*)d_out;

    dim3 gproj(DMODEL / 64, MROWS / 128);   // (16, 32)
    gemm_proj_kernel<<<gproj, 256>>>(q, Wq, 0);
    gemm_proj_kernel<<<gproj, 256>>>(k, Wk, 1);
    gemm_proj_kernel<<<gproj, 256>>>(v, Wv, 2);

    attn_kernel<<<dim3(SEQ / 64, NHEADS, BATCH), 256>>>();

    gemm_out_kernel<<<gproj, 256>>>(Wo, out);
}

// round 2
// speedup vs baseline: 1.0590x; 1.0590x over previous
#include <cuda_runtime.h>
#include <math.h>

#define NHEADS 16
#define BATCH  2
#define SEQ    2048
#define DMODEL 1024
#define HID    64
#define MROWS  (BATCH*SEQ)   // 4096
#define NORM   0.125f        // 1/sqrt(64)

// Scratch (device globals: no allocation allowed in kernel_launch)
__device__ float g_Q[NHEADS*BATCH*SEQ*HID];   // [h][b][s][e]
__device__ float g_K[NHEADS*BATCH*SEQ*HID];
__device__ float g_V[NHEADS*BATCH*SEQ*HID];
__device__ float g_Hd[MROWS*DMODEL];          // [b][s][h*64+e]

// ---------------------------------------------------------------------------
// Projection GEMM: BM=128, BN=128 (2 heads), BK=16, 256 threads, 8x8 microtile
// (quadrant split: rows {tm*4+i, 64+tm*4+i}, cols {tn*4+j, 64+tn*4+j}).
// ---------------------------------------------------------------------------
__global__ __launch_bounds__(256, 2)
void gemm_proj_kernel(const float* __restrict__ X,
                      const float* __restrict__ W,
                      int which)
{
    __shared__ __align__(16) float As[16][132];  // transposed [k][m]
    __shared__ __align__(16) float Bs[16][132];  // natural    [k][n]

    const int tid = threadIdx.x;
    const int tn = tid & 15, tm = tid >> 4;
    const int h0 = blockIdx.x * 2;               // two heads per block
    const int m0 = blockIdx.y * 128;
    const float* W0 = W + (size_t)h0 * DMODEL * HID;
    const float* W1 = W0 + (size_t)DMODEL * HID;

    float acc[8][8];
    #pragma unroll
    for (int i = 0; i < 8; i++)
        #pragma unroll
        for (int j = 0; j < 8; j++) acc[i][j] = 0.f;

    for (int k0 = 0; k0 < DMODEL; k0 += 16) {
        // A tile: 128x16 -> 512 float4, 2/thread, store transposed
        #pragma unroll
        for (int t = 0; t < 2; t++) {
            int f = tid + t * 256;
            int row = f >> 2;
            int kq = (f & 3) * 4;
            float4 a4 = *(const float4*)(X + (size_t)(m0 + row) * DMODEL + k0 + kq);
            As[kq + 0][row] = a4.x; As[kq + 1][row] = a4.y;
            As[kq + 2][row] = a4.z; As[kq + 3][row] = a4.w;
        }
        // B tile: 16x128 (two heads side by side) -> 512 float4, 2/thread
        #pragma unroll
        for (int t = 0; t < 2; t++) {
            int f = tid + t * 256;
            int kk = f >> 5;
            int c4 = (f & 31) * 4;
            const float* src = (c4 < 64)
                ? (W0 + (size_t)(k0 + kk) * HID + c4)
                : (W1 + (size_t)(k0 + kk) * HID + (c4 - 64));
            *(float4*)&Bs[kk][c4] = *(const float4*)src;
        }
        __syncthreads();

        #pragma unroll
        for (int kk = 0; kk < 16; kk++) {
            float4 a0 = *(float4*)&As[kk][tm * 4];
            float4 a1 = *(float4*)&As[kk][64 + tm * 4];
            float4 b0 = *(float4*)&Bs[kk][tn * 4];
            float4 b1 = *(float4*)&Bs[kk][64 + tn * 4];
            float a[8] = {a0.x,a0.y,a0.z,a0.w,a1.x,a1.y,a1.z,a1.w};
            float b[8] = {b0.x,b0.y,b0.z,b0.w,b1.x,b1.y,b1.z,b1.w};
            #pragma unroll
            for (int i = 0; i < 8; i++)
                #pragma unroll
                for (int j = 0; j < 8; j++) acc[i][j] += a[i] * b[j];
        }
        __syncthreads();
    }

    float* Out = (which == 0) ? g_Q : (which == 1) ? g_K : g_V;
    #pragma unroll
    for (int jh = 0; jh < 2; jh++) {
        float* Oh = Out + (size_t)(h0 + jh) * BATCH * SEQ * HID;
        #pragma unroll
        for (int ih = 0; ih < 2; ih++)
            #pragma unroll
            for (int i = 0; i < 4; i++) {
                int m = m0 + ih * 64 + tm * 4 + i;
                int b_ = m >> 11, s_ = m & 2047;
                float4 o = make_float4(acc[ih*4+i][jh*4+0], acc[ih*4+i][jh*4+1],
                                       acc[ih*4+i][jh*4+2], acc[ih*4+i][jh*4+3]);
                *(float4*)(Oh + ((size_t)b_ * SEQ + s_) * HID + tn * 4) = o;
            }
    }
}

// ---------------------------------------------------------------------------
// Output projection: same tiling, B from flat Wo[1024][1024].
// ---------------------------------------------------------------------------
__global__ __launch_bounds__(256, 2)
void gemm_out_kernel(const float* __restrict__ W,
                     float* __restrict__ Out)
{
    __shared__ __align__(16) float As[16][132];
    __shared__ __align__(16) float Bs[16][132];

    const int tid = threadIdx.x;
    const int tn = tid & 15, tm = tid >> 4;
    const int n0 = blockIdx.x * 128;
    const int m0 = blockIdx.y * 128;

    float acc[8][8];
    #pragma unroll
    for (int i = 0; i < 8; i++)
        #pragma unroll
        for (int j = 0; j < 8; j++) acc[i][j] = 0.f;

    for (int k0 = 0; k0 < DMODEL; k0 += 16) {
        #pragma unroll
        for (int t = 0; t < 2; t++) {
            int f = tid + t * 256;
            int row = f >> 2;
            int kq = (f & 3) * 4;
            float4 a4 = *(const float4*)(g_Hd + (size_t)(m0 + row) * DMODEL + k0 + kq);
            As[kq + 0][row] = a4.x; As[kq + 1][row] = a4.y;
            As[kq + 2][row] = a4.z; As[kq + 3][row] = a4.w;
        }
        #pragma unroll
        for (int t = 0; t < 2; t++) {
            int f = tid + t * 256;
            int kk = f >> 5;
            int c4 = (f & 31) * 4;
            *(float4*)&Bs[kk][c4] =
                *(const float4*)(W + (size_t)(k0 + kk) * DMODEL + n0 + c4);
        }
        __syncthreads();

        #pragma unroll
        for (int kk = 0; kk < 16; kk++) {
            float4 a0 = *(float4*)&As[kk][tm * 4];
            float4 a1 = *(float4*)&As[kk][64 + tm * 4];
            float4 b0 = *(float4*)&Bs[kk][tn * 4];
            float4 b1 = *(float4*)&Bs[kk][64 + tn * 4];
            float a[8] = {a0.x,a0.y,a0.z,a0.w,a1.x,a1.y,a1.z,a1.w};
            float b[8] = {b0.x,b0.y,b0.z,b0.w,b1.x,b1.y,b1.z,b1.w};
            #pragma unroll
            for (int i = 0; i < 8; i++)
                #pragma unroll
                for (int j = 0; j < 8; j++) acc[i][j] += a[i] * b[j];
        }
        __syncthreads();
    }

    #pragma unroll
    for (int ih = 0; ih < 2; ih++)
        #pragma unroll
        for (int i = 0; i < 4; i++) {
            int m = m0 + ih * 64 + tm * 4 + i;
            #pragma unroll
            for (int jh = 0; jh < 2; jh++) {
                float4 o = make_float4(acc[ih*4+i][jh*4+0], acc[ih*4+i][jh*4+1],
                                       acc[ih*4+i][jh*4+2], acc[ih*4+i][jh*4+3]);
                *(float4*)(Out + (size_t)m * DMODEL + n0 + jh * 64 + tn * 4) = o;
            }
        }
}

// ---------------------------------------------------------------------------
// Flash attention fp32. BQ=128 q-rows x BKt=64 keys per tile, 256 threads.
// Microtile: rows {tq*4+i, 64+tq*4+i}, 4 k-cols (tk*4+j). All smem natural
// row-major in float4 chunks with XOR swizzle: phys_chunk = c ^ ((row>>2)&7).
// Dynamic smem: Qs 2048 + Ks 1024 + Vs 1024 + Ss 2048 float4 = 96KB.
// ---------------------------------------------------------------------------
__global__ __launch_bounds__(256, 2)
void attn_kernel()
{
    extern __shared__ float4 sm4[];
    float4* Qs = sm4;           // [128][16]
    float4* Ks = sm4 + 2048;    // [64][16]
    float4* Vs = sm4 + 3072;    // [64][16]
    float4* Ss = sm4 + 4096;    // [128][16]

    const int tid = threadIdx.x;
    const int tk = tid & 15;    // k-col group (also e-col group in PV)
    const int tq = tid >> 4;    // q-row group
    const int swq = tq & 7;     // (q>>2)&7 for q = tq*4+i and 64+tq*4+i
    const int swk = tk & 7;     // (k>>2)&7 for k = tk*4+j

    const int q0 = blockIdx.x * 128;
    const int h  = blockIdx.y;
    const int b  = blockIdx.z;
    const size_t base4 = (((size_t)h * BATCH + b) * SEQ) * 16;  // float4 units
    const float4* Qg = (const float4*)g_Q + base4;
    const float4* Kg = (const float4*)g_K + base4;
    const float4* Vg = (const float4*)g_V + base4;

    // Load Q tile (scaled): 2048 float4, 8/thread, swizzled store
    #pragma unroll
    for (int t = 0; t < 8; t++) {
        int f = tid + t * 256;
        int r = f >> 4, c = f & 15;
        float4 a = Qg[(size_t)(q0 + r) * 16 + c];
        a.x *= NORM; a.y *= NORM; a.z *= NORM; a.w *= NORM;
        Qs[r * 16 + (c ^ ((r >> 2) & 7))] = a;
    }

    float m_i[8], l_i[8], acc[8][4];
    #pragma unroll
    for (int i = 0; i < 8; i++) {
        m_i[i] = -1e30f; l_i[i] = 0.f;
        #pragma unroll
        for (int j = 0; j < 4; j++) acc[i][j] = 0.f;
    }

    for (int kt = 0; kt < SEQ / 64; kt++) {
        const int k0 = kt * 64;
        // Load K and V tiles: 1024 float4 each, 4/thread each
        #pragma unroll
        for (int t = 0; t < 4; t++) {
            int f = tid + t * 256;
            int r = f >> 4, c = f & 15;
            int pc = r * 16 + (c ^ ((r >> 2) & 7));
            Ks[pc] = Kg[(size_t)(k0 + r) * 16 + c];
            Vs[pc] = Vg[(size_t)(k0 + r) * 16 + c];
        }
        __syncthreads();

        // S = Q K^T, vectorized over e in float4 chunks
        float s[8][4];
        #pragma unroll
        for (int i = 0; i < 8; i++)
            #pragma unroll
            for (int j = 0; j < 4; j++) s[i][j] = 0.f;

        #pragma unroll 4
        for (int c = 0; c < 16; c++) {
            float4 kr[4];
            #pragma unroll
            for (int j = 0; j < 4; j++)
                kr[j] = Ks[(tk * 4 + j) * 16 + (c ^ swk)];
            #pragma unroll
            for (int hf = 0; hf < 2; hf++)
                #pragma unroll
                for (int i = 0; i < 4; i++) {
                    float4 qv = Qs[(hf * 64 + tq * 4 + i) * 16 + (c ^ swq)];
                    int ii = hf * 4 + i;
                    #pragma unroll
                    for (int j = 0; j < 4; j++)
                        s[ii][j] += qv.x * kr[j].x + qv.y * kr[j].y
                                  + qv.z * kr[j].z + qv.w * kr[j].w;
                }
        }

        // Online softmax per row (reduce across 16 tk lanes)
        #pragma unroll
        for (int ii = 0; ii < 8; ii++) {
            float mt = fmaxf(fmaxf(s[ii][0], s[ii][1]), fmaxf(s[ii][2], s[ii][3]));
            #pragma unroll
            for (int off = 8; off >= 1; off >>= 1)
                mt = fmaxf(mt, __shfl_xor_sync(0xffffffffu, mt, off));
            float mn = fmaxf(m_i[ii], mt);
            float al = __expf(m_i[ii] - mn);
            float lt = 0.f;
            #pragma unroll
            for (int j = 0; j < 4; j++) {
                float p = __expf(s[ii][j] - mn);
                s[ii][j] = p; lt += p;
            }
            #pragma unroll
            for (int off = 8; off >= 1; off >>= 1)
                lt += __shfl_xor_sync(0xffffffffu, lt, off);
            l_i[ii] = l_i[ii] * al + lt;
            m_i[ii] = mn;
            #pragma unroll
            for (int j = 0; j < 4; j++) acc[ii][j] *= al;
        }

        // Store P (swizzled, float4 rows: logical chunk tk)
        #pragma unroll
        for (int hf = 0; hf < 2; hf++)
            #pragma unroll
            for (int i = 0; i < 4; i++) {
                int q = hf * 64 + tq * 4 + i;
                int ii = hf * 4 + i;
                Ss[q * 16 + (tk ^ swq)] =
                    make_float4(s[ii][0], s[ii][1], s[ii][2], s[ii][3]);
            }
        __syncthreads();

        // O += P V, vectorized over k in float4 chunks
        #pragma unroll 4
        for (int c = 0; c < 16; c++) {
            float4 vr[4];
            int swc = c & 7;
            #pragma unroll
            for (int r = 0; r < 4; r++)
                vr[r] = Vs[(c * 4 + r) * 16 + (tk ^ swc)];
            #pragma unroll
            for (int hf = 0; hf < 2; hf++)
                #pragma unroll
                for (int i = 0; i < 4; i++) {
                    float4 pv = Ss[(hf * 64 + tq * 4 + i) * 16 + (c ^ swq)];
                    int ii = hf * 4 + i;
                    acc[ii][0] += pv.x*vr[0].x + pv.y*vr[1].x + pv.z*vr[2].x + pv.w*vr[3].x;
                    acc[ii][1] += pv.x*vr[0].y + pv.y*vr[1].y + pv.z*vr[2].y + pv.w*vr[3].y;
                    acc[ii][2] += pv.x*vr[0].z + pv.y*vr[1].z + pv.z*vr[2].z + pv.w*vr[3].z;
                    acc[ii][3] += pv.x*vr[0].w + pv.y*vr[1].w + pv.z*vr[2].w + pv.w*vr[3].w;
                }
        }
        __syncthreads();
    }

    // Normalize and write heads: [b][s][h*64+e]
    #pragma unroll
    for (int hf = 0; hf < 2; hf++)
        #pragma unroll
        for (int i = 0; i < 4; i++) {
            int ii = hf * 4 + i;
            int q = q0 + hf * 64 + tq * 4 + i;
            float inv = 1.f / l_i[ii];
            float4 o = make_float4(acc[ii][0]*inv, acc[ii][1]*inv,
                                   acc[ii][2]*inv, acc[ii][3]*inv);
            *(float4*)(g_Hd + ((size_t)b * SEQ + q) * DMODEL + h * HID + tk * 4) = o;
        }
}

// ---------------------------------------------------------------------------
extern "C" void kernel_launch(void* const* d_in, const int* in_sizes, int n_in,
                              void* d_out, int out_size)
{
    const float* q  = (const float*)d_in[0];
    const float* k  = (const float*)d_in[1];
    const float* v  = (const float*)d_in[2];
    const float* Wq = (const float*)d_in[3];
    const float* Wk = (const float*)d_in[4];
    const float* Wv = (const float*)d_in[5];
    const float* Wo = (const float*)d_in[6];
    float* out = (float*)d_out;

    cudaFuncSetAttribute(attn_kernel,
                         cudaFuncAttributeMaxDynamicSharedMemorySize, 98304);

    dim3 gproj(DMODEL / 128, MROWS / 128);   // (8, 32)
    gemm_proj_kernel<<<gproj, 256>>>(q, Wq, 0);
    gemm_proj_kernel<<<gproj, 256>>>(k, Wk, 1);
    gemm_proj_kernel<<<gproj, 256>>>(v, Wv, 2);

    attn_kernel<<<dim3(SEQ / 128, NHEADS, BATCH), 256, 98304>>>();

    gemm_out_kernel<<<gproj, 256>>>(Wo, out);
}

// round 5
// speedup vs baseline: 2.1269x; 2.0083x over previous
#include <cuda_runtime.h>
#include <cuda_fp16.h>
#include <math.h>
#include <stdint.h>

#define NHEADS 16
#define BATCH  2
#define SEQ    2048
#define DMODEL 1024
#define HID    64
#define MROWS  (BATCH*SEQ)   // 4096
#define NORM   0.125f        // 1/sqrt(64)

// Scratch (device globals: no allocation allowed in kernel_launch)
__device__ float g_Q [NHEADS*BATCH*SEQ*HID];   // [h][b][s][e]
__device__ float g_K [NHEADS*BATCH*SEQ*HID];   // [h][b][s][e]
__device__ float g_Vt[NHEADS*BATCH*HID*SEQ];   // [h][b][e][s]  (transposed!)
__device__ float g_Hd[MROWS*DMODEL];           // [b][s][h*64+e]

// ---------------------------------------------------------------------------
// fp16 split helpers: x = hi + lo (each fp16), packed as half2 (even,odd)
// ---------------------------------------------------------------------------
__device__ __forceinline__ void split2(float x, float y,
                                       uint32_t& hi, uint32_t& lo) {
    __half hx = __float2half_rn(x), hy = __float2half_rn(y);
    __half2 H = __halves2half2(hx, hy);
    __half2 L = __floats2half2_rn(x - __half2float(hx), y - __half2float(hy));
    hi = *reinterpret_cast<uint32_t*>(&H);
    lo = *reinterpret_cast<uint32_t*>(&L);
}

// D += A(16x16 row) * B(16x8 col), fp16 in, fp32 accum
__device__ __forceinline__ void mma16(float4& d,
                                      uint32_t a0, uint32_t a1, uint32_t a2, uint32_t a3,
                                      uint32_t b0, uint32_t b1) {
    asm volatile(
        "mma.sync.aligned.m16n8k16.row.col.f32.f16.f16.f32 "
        "{%0,%1,%2,%3},{%4,%5,%6,%7},{%8,%9},{%0,%1,%2,%3};"
        : "+f"(d.x), "+f"(d.y), "+f"(d.z), "+f"(d.w)
        : "r"(a0), "r"(a1), "r"(a2), "r"(a3), "r"(b0), "r"(b1));
}

// 3-MMA compensated product: acc += (Ah+Al)(Bh+Bl) - Al*Bl
__device__ __forceinline__ void mma3(float4& d, const uint32_t ah[4],
                                     const uint32_t al[4],
                                     uint32_t bh0, uint32_t bh1,
                                     uint32_t bl0, uint32_t bl1) {
    mma16(d, ah[0], ah[1], ah[2], ah[3], bh0, bh1);
    mma16(d, ah[0], ah[1], ah[2], ah[3], bl0, bl1);
    mma16(d, al[0], al[1], al[2], al[3], bh0, bh1);
}

// ---------------------------------------------------------------------------
// GEMM: C[4096 x 128-tile] = A[4096,1024] * B[1024,N], compensated fp16.
// BM=128, BN=128, BK=32 (16 half2 pairs), 256 thr = 8 warps (4m x 2n).
// Warp tile 32m x 64n: mf=2 x nf=8 m16n8k16 frags; 2 k-steps per tile.
// Smem rows: 16 pairs + 4 pad = stride 20 words (20 mod 32 -> g*20+qd all
// distinct mod 32: fragment loads conflict-free).
// which: 0=Q, 1=K ([h][b][s][e]), 2=V transposed ([h][b][e][s]), 3=out-proj.
// ---------------------------------------------------------------------------
__global__ __launch_bounds__(256, 2)
void gemm_h2(const float* __restrict__ A,
             const float* __restrict__ B,
             float* __restrict__ Out,
             int which)
{
    __shared__ uint32_t Ah[128 * 20], Al[128 * 20];
    __shared__ uint32_t Bh[128 * 20], Bl[128 * 20];   // [n][kpair]

    const int tid  = threadIdx.x;
    const int lane = tid & 31;
    const int wid  = tid >> 5;
    const int g    = lane >> 2;
    const int qd   = lane & 3;
    const int wm   = wid >> 1;
    const int wn   = wid & 1;
    const int m0   = blockIdx.y * 128;
    const int bx   = blockIdx.x;

    float4 acc[2][8];
    #pragma unroll
    for (int i = 0; i < 2; i++)
        #pragma unroll
        for (int j = 0; j < 8; j++) acc[i][j] = make_float4(0.f, 0.f, 0.f, 0.f);

    // B-load thread mapping: 4 n-cols x 2 k-pairs per thread
    const int bn4 = (tid & 31) * 4;      // n col base (0..124)
    const int bp2 = (tid >> 5) * 2;      // k-pair base (0..14)

    for (int k0 = 0; k0 < DMODEL; k0 += 32) {
        // ---- A tile 128x32: 4 float4/thread; pairs 2c,2c+1 per float4
        #pragma unroll
        for (int t = 0; t < 4; t++) {
            int f = tid + t * 256;
            int row = f >> 3, c = f & 7;
            float4 a = *(const float4*)(A + (size_t)(m0 + row) * DMODEL + k0 + c * 4);
            uint32_t h0, l0, h1, l1;
            split2(a.x, a.y, h0, l0);
            split2(a.z, a.w, h1, l1);
            int idx = row * 20 + 2 * c;
            *(uint2*)&Ah[idx] = make_uint2(h0, h1);
            *(uint2*)&Al[idx] = make_uint2(l0, l1);
        }
        // ---- B tile -> [n][kpair]: per thread 2 pairs x 4 cols
        #pragma unroll
        for (int pi = 0; pi < 2; pi++) {
            int p = bp2 + pi;                   // k-pair
            const float *r0, *r1;
            if (which < 3) {
                int head = bx * 2 + (bn4 >= 64);
                int col  = bn4 & 63;
                r0 = B + ((size_t)head * DMODEL + k0 + 2 * p) * HID + col;
                r1 = r0 + HID;
            } else {
                r0 = B + (size_t)(k0 + 2 * p) * DMODEL + bx * 128 + bn4;
                r1 = r0 + DMODEL;
            }
            float4 v0 = *(const float4*)r0;     // k even
            float4 v1 = *(const float4*)r1;     // k odd
            const float e0[4] = {v0.x, v0.y, v0.z, v0.w};
            const float e1[4] = {v1.x, v1.y, v1.z, v1.w};
            #pragma unroll
            for (int j = 0; j < 4; j++) {
                uint32_t h, l;
                split2(e0[j], e1[j], h, l);
                Bh[(bn4 + j) * 20 + p] = h;
                Bl[(bn4 + j) * 20 + p] = l;
            }
        }
        __syncthreads();

        #pragma unroll
        for (int s = 0; s < 2; s++) {           // k16 steps
            uint32_t ah[2][4], al[2][4];
            #pragma unroll
            for (int mf = 0; mf < 2; mf++) {
                int r0 = (wm * 32 + mf * 16 + g) * 20;
                int r1 = r0 + 8 * 20;
                int p0 = s * 8 + qd, p1 = p0 + 4;
                ah[mf][0] = Ah[r0 + p0]; ah[mf][1] = Ah[r1 + p0];
                ah[mf][2] = Ah[r0 + p1]; ah[mf][3] = Ah[r1 + p1];
                al[mf][0] = Al[r0 + p0]; al[mf][1] = Al[r1 + p0];
                al[mf][2] = Al[r0 + p1]; al[mf][3] = Al[r1 + p1];
            }
            #pragma unroll
            for (int nf = 0; nf < 8; nf++) {
                int n = (wn * 64 + nf * 8 + g) * 20;
                int p0 = s * 8 + qd, p1 = p0 + 4;
                uint32_t bh0 = Bh[n + p0], bh1 = Bh[n + p1];
                uint32_t bl0 = Bl[n + p0], bl1 = Bl[n + p1];
                mma3(acc[0][nf], ah[0], al[0], bh0, bh1, bl0, bl1);
                mma3(acc[1][nf], ah[1], al[1], bh0, bh1, bl0, bl1);
            }
        }
        __syncthreads();
    }

    // Epilogue. D frag: (x,y)=row g cols (2qd,2qd+1); (z,w)=row g+8.
    #pragma unroll
    for (int mf = 0; mf < 2; mf++) {
        int mA = m0 + wm * 32 + mf * 16 + g;
        int mB = mA + 8;
        #pragma unroll
        for (int nf = 0; nf < 8; nf++) {
            float4 c = acc[mf][nf];
            if (which < 2) {
                float* O = (which == 0) ? g_Q : g_K;
                int head = bx * 2 + wn;
                int e = nf * 8 + 2 * qd;
                int bA = mA >> 11, sA = mA & 2047;
                int bB = mB >> 11, sB = mB & 2047;
                *(float2*)(O + (((size_t)head * BATCH + bA) * SEQ + sA) * HID + e) =
                    make_float2(c.x, c.y);
                *(float2*)(O + (((size_t)head * BATCH + bB) * SEQ + sB) * HID + e) =
                    make_float2(c.z, c.w);
            } else if (which == 2) {
                int head = bx * 2 + wn;
                int e = nf * 8 + 2 * qd;
                int bA = mA >> 11, sA = mA & 2047;
                int bB = mB >> 11, sB = mB & 2047;
                size_t base = ((size_t)head * BATCH) * HID * SEQ;
                g_Vt[base + ((size_t)bA * HID + e    ) * SEQ + sA] = c.x;
                g_Vt[base + ((size_t)bA * HID + e + 1) * SEQ + sA] = c.y;
                g_Vt[base + ((size_t)bB * HID + e    ) * SEQ + sB] = c.z;
                g_Vt[base + ((size_t)bB * HID + e + 1) * SEQ + sB] = c.w;
            } else {
                int n = bx * 128 + wn * 64 + nf * 8 + 2 * qd;
                *(float2*)(Out + (size_t)mA * DMODEL + n) = make_float2(c.x, c.y);
                *(float2*)(Out + (size_t)mB * DMODEL + n) = make_float2(c.z, c.w);
            }
        }
    }
}

// ---------------------------------------------------------------------------
// Flash attention, compensated fp16. BQ=128 q-rows, 8 warps x 16 rows.
// K tile 64 keys. All smem [row][32 kpairs + 4 pad] stride 36 (mod 32 == 4 ->
// fragment loads conflict-free).
// ---------------------------------------------------------------------------
__global__ __launch_bounds__(256, 2)
void attn_h2()
{
    extern __shared__ uint32_t sm[];
    uint32_t* Qh = sm;                 // [128][36]
    uint32_t* Ql = Qh + 128 * 36;
    uint32_t* Kh = Ql + 128 * 36;      // [64][36]
    uint32_t* Kl = Kh + 64 * 36;
    uint32_t* Vh = Kl + 64 * 36;       // [64][36]  (V^T: [e][keypair])
    uint32_t* Vl = Vh + 64 * 36;
    uint32_t* Ph = Vl + 64 * 36;       // [128][36]
    uint32_t* Pl = Ph + 128 * 36;

    const int tid  = threadIdx.x;
    const int lane = tid & 31;
    const int g    = lane >> 2;
    const int qd   = lane & 3;
    const int wq0  = (tid >> 5) * 16;

    const int q0 = blockIdx.x * 128;
    const int h  = blockIdx.y;
    const int b  = blockIdx.z;

    const float* Qg  = g_Q  + ((size_t)h * BATCH + b) * SEQ * HID;
    const float* Kg  = g_K  + ((size_t)h * BATCH + b) * SEQ * HID;
    const float* Vtg = g_Vt + ((size_t)h * BATCH + b) * HID * SEQ;

    // Load Q tile (scaled): 2048 float4, 8/thread
    #pragma unroll
    for (int t = 0; t < 8; t++) {
        int f = tid + t * 256;
        int row = f >> 4, c = f & 15;
        float4 a = *(const float4*)(Qg + (size_t)(q0 + row) * HID + c * 4);
        uint32_t h0, l0, h1, l1;
        split2(a.x * NORM, a.y * NORM, h0, l0);
        split2(a.z * NORM, a.w * NORM, h1, l1);
        int idx = row * 36 + 2 * c;
        *(uint2*)&Qh[idx] = make_uint2(h0, h1);
        *(uint2*)&Ql[idx] = make_uint2(l0, l1);
    }

    float4 o[8];
    #pragma unroll
    for (int j = 0; j < 8; j++) o[j] = make_float4(0.f, 0.f, 0.f, 0.f);
    float mA = -1e30f, mB = -1e30f, lA = 0.f, lB = 0.f;

    for (int kt = 0; kt < SEQ / 64; kt++) {
        const int k0 = kt * 64;
        __syncthreads();   // prev iter done reading K/V
        // K tile [key][e] and V^T tile [e][key]: 1024 float4 each, 4/thread
        #pragma unroll
        for (int t = 0; t < 4; t++) {
            int f = tid + t * 256;
            int row = f >> 4, c = f & 15;
            int idx = row * 36 + 2 * c;
            float4 kv = *(const float4*)(Kg + (size_t)(k0 + row) * HID + c * 4);
            uint32_t h0, l0, h1, l1;
            split2(kv.x, kv.y, h0, l0);
            split2(kv.z, kv.w, h1, l1);
            *(uint2*)&Kh[idx] = make_uint2(h0, h1);
            *(uint2*)&Kl[idx] = make_uint2(l0, l1);
            float4 vv = *(const float4*)(Vtg + (size_t)row * SEQ + k0 + c * 4);
            split2(vv.x, vv.y, h0, l0);
            split2(vv.z, vv.w, h1, l1);
            *(uint2*)&Vh[idx] = make_uint2(h0, h1);
            *(uint2*)&Vl[idx] = make_uint2(l0, l1);
        }
        __syncthreads();

        // ---- S = Q K^T : 4 k16 steps over e=64
        float4 s[8];
        #pragma unroll
        for (int j = 0; j < 8; j++) s[j] = make_float4(0.f, 0.f, 0.f, 0.f);

        #pragma unroll
        for (int st = 0; st < 4; st++) {
            int r0 = (wq0 + g) * 36, r1 = r0 + 8 * 36;
            int p0 = st * 8 + qd, p1 = p0 + 4;
            uint32_t ah[4] = {Qh[r0 + p0], Qh[r1 + p0], Qh[r0 + p1], Qh[r1 + p1]};
            uint32_t al[4] = {Ql[r0 + p0], Ql[r1 + p0], Ql[r0 + p1], Ql[r1 + p1]};
            #pragma unroll
            for (int nf = 0; nf < 8; nf++) {
                int n = (nf * 8 + g) * 36;
                mma3(s[nf], ah, al, Kh[n + p0], Kh[n + p1], Kl[n + p0], Kl[n + p1]);
            }
        }

        // ---- online softmax. (x,y): row g; (z,w): row g+8
        float mtA = -1e30f, mtB = -1e30f;
        #pragma unroll
        for (int nf = 0; nf < 8; nf++) {
            mtA = fmaxf(mtA, fmaxf(s[nf].x, s[nf].y));
            mtB = fmaxf(mtB, fmaxf(s[nf].z, s[nf].w));
        }
        mtA = fmaxf(mtA, __shfl_xor_sync(0xffffffffu, mtA, 1));
        mtA = fmaxf(mtA, __shfl_xor_sync(0xffffffffu, mtA, 2));
        mtB = fmaxf(mtB, __shfl_xor_sync(0xffffffffu, mtB, 1));
        mtB = fmaxf(mtB, __shfl_xor_sync(0xffffffffu, mtB, 2));

        float mnA = fmaxf(mA, mtA), mnB = fmaxf(mB, mtB);
        float alA = __expf(mA - mnA), alB = __expf(mB - mnB);
        float sumA = 0.f, sumB = 0.f;
        #pragma unroll
        for (int nf = 0; nf < 8; nf++) {
            s[nf].x = __expf(s[nf].x - mnA);
            s[nf].y = __expf(s[nf].y - mnA);
            s[nf].z = __expf(s[nf].z - mnB);
            s[nf].w = __expf(s[nf].w - mnB);
            sumA += s[nf].x + s[nf].y;
            sumB += s[nf].z + s[nf].w;
        }
        sumA += __shfl_xor_sync(0xffffffffu, sumA, 1);
        sumA += __shfl_xor_sync(0xffffffffu, sumA, 2);
        sumB += __shfl_xor_sync(0xffffffffu, sumB, 1);
        sumB += __shfl_xor_sync(0xffffffffu, sumB, 2);
        lA = lA * alA + sumA; mA = mnA;
        lB = lB * alB + sumB; mB = mnB;
        #pragma unroll
        for (int nf = 0; nf < 8; nf++) {
            o[nf].x *= alA; o[nf].y *= alA;
            o[nf].z *= alB; o[nf].w *= alB;
        }

        // ---- store P split (cols 2qd,2qd+1 -> pair nf*4+qd; warp-private rows)
        {
            int r0 = (wq0 + g) * 36, r1 = r0 + 8 * 36;
            #pragma unroll
            for (int nf = 0; nf < 8; nf++) {
                uint32_t hh, ll;
                int pidx = nf * 4 + qd;
                split2(s[nf].x, s[nf].y, hh, ll);
                Ph[r0 + pidx] = hh; Pl[r0 + pidx] = ll;
                split2(s[nf].z, s[nf].w, hh, ll);
                Ph[r1 + pidx] = hh; Pl[r1 + pidx] = ll;
            }
        }
        __syncwarp();

        // ---- O += P V : 4 k16 steps over keys=64
        #pragma unroll
        for (int st = 0; st < 4; st++) {
            int r0 = (wq0 + g) * 36, r1 = r0 + 8 * 36;
            int p0 = st * 8 + qd, p1 = p0 + 4;
            uint32_t ah[4] = {Ph[r0 + p0], Ph[r1 + p0], Ph[r0 + p1], Ph[r1 + p1]};
            uint32_t al[4] = {Pl[r0 + p0], Pl[r1 + p0], Pl[r0 + p1], Pl[r1 + p1]};
            #pragma unroll
            for (int nf = 0; nf < 8; nf++) {
                int n = (nf * 8 + g) * 36;
                mma3(o[nf], ah, al, Vh[n + p0], Vh[n + p1], Vl[n + p0], Vl[n + p1]);
            }
        }
    }

    // Normalize, write heads: g_Hd[b][q][h*64+e]
    float invA = 1.f / lA, invB = 1.f / lB;
    int qA = q0 + wq0 + g, qB = qA + 8;
    #pragma unroll
    for (int nf = 0; nf < 8; nf++) {
        int e = nf * 8 + 2 * qd;
        *(float2*)(g_Hd + ((size_t)b * SEQ + qA) * DMODEL + h * HID + e) =
            make_float2(o[nf].x * invA, o[nf].y * invA);
        *(float2*)(g_Hd + ((size_t)b * SEQ + qB) * DMODEL + h * HID + e) =
            make_float2(o[nf].z * invB, o[nf].w * invB);
    }
}

#define ATTN_SMEM ((2*128*36 + 2*64*36 + 2*64*36 + 2*128*36) * 4)  // 110592 B

// ---------------------------------------------------------------------------
extern "C" void kernel_launch(void* const* d_in, const int* in_sizes, int n_in,
                              void* d_out, int out_size)
{
    const float* q  = (const float*)d_in[0];
    const float* k  = (const float*)d_in[1];
    const float* v  = (const float*)d_in[2];
    const float* Wq = (const float*)d_in[3];
    const float* Wk = (const float*)d_in[4];
    const float* Wv = (const float*)d_in[5];
    const float* Wo = (const float*)d_in[6];
    float* out = (float*)d_out;

    cudaFuncSetAttribute(attn_h2,
        cudaFuncAttributeMaxDynamicSharedMemorySize, ATTN_SMEM);

    float* hd_ptr;
    cudaGetSymbolAddress((void**)&hd_ptr, g_Hd);

    dim3 gproj(DMODEL / 128, MROWS / 128);   // (8, 32)
    gemm_h2<<<gproj, 256>>>(q, Wq, nullptr, 0);
    gemm_h2<<<gproj, 256>>>(k, Wk, nullptr, 1);
    gemm_h2<<<gproj, 256>>>(v, Wv, nullptr, 2);

    attn_h2<<<dim3(SEQ / 128, NHEADS, BATCH), 256, ATTN_SMEM>>>();

    gemm_h2<<<gproj, 256>>>(hd_ptr, Wo, out, 3);
}

// round 6
// speedup vs baseline: 2.4987x; 1.1748x over previous
#include <cuda_runtime.h>
#include <cuda_fp16.h>
#include <math.h>
#include <stdint.h>

#define NHEADS 16
#define BATCH  2
#define SEQ    2048
#define DMODEL 1024
#define HID    64
#define MROWS  (BATCH*SEQ)   // 4096
#define NORM   0.125f        // 1/sqrt(64)

// Scratch (device globals: no allocation allowed in kernel_launch)
__device__ float g_Q [NHEADS*BATCH*SEQ*HID];   // [h][b][s][e]
__device__ float g_K [NHEADS*BATCH*SEQ*HID];   // [h][b][s][e]
__device__ float g_Vt[NHEADS*BATCH*HID*SEQ];   // [h][b][e][s]  (transposed!)
__device__ float g_Hd[MROWS*DMODEL];           // [b][s][h*64+e]

// ---------------------------------------------------------------------------
// helpers
// ---------------------------------------------------------------------------
__device__ __forceinline__ void split2(float x, float y,
                                       uint32_t& hi, uint32_t& lo) {
    __half hx = __float2half_rn(x), hy = __float2half_rn(y);
    __half2 H = __halves2half2(hx, hy);
    __half2 L = __floats2half2_rn(x - __half2float(hx), y - __half2float(hy));
    hi = *reinterpret_cast<uint32_t*>(&H);
    lo = *reinterpret_cast<uint32_t*>(&L);
}

__device__ __forceinline__ uint32_t smem_u32(const void* p) {
    return (uint32_t)__cvta_generic_to_shared(p);
}

__device__ __forceinline__ void ldsm_x4(uint32_t& r0, uint32_t& r1,
                                        uint32_t& r2, uint32_t& r3,
                                        uint32_t addr) {
    asm volatile("ldmatrix.sync.aligned.m8n8.x4.shared.b16 {%0,%1,%2,%3},[%4];"
        : "=r"(r0), "=r"(r1), "=r"(r2), "=r"(r3) : "r"(addr));
}

// D += A(16x16 row) * B(16x8 col), fp16 in, fp32 accum
__device__ __forceinline__ void mma16(float4& d,
                                      uint32_t a0, uint32_t a1, uint32_t a2, uint32_t a3,
                                      uint32_t b0, uint32_t b1) {
    asm volatile(
        "mma.sync.aligned.m16n8k16.row.col.f32.f16.f16.f32 "
        "{%0,%1,%2,%3},{%4,%5,%6,%7},{%8,%9},{%0,%1,%2,%3};"
        : "+f"(d.x), "+f"(d.y), "+f"(d.z), "+f"(d.w)
        : "r"(a0), "r"(a1), "r"(a2), "r"(a3), "r"(b0), "r"(b1));
}

// 3-MMA compensated product: acc += Ah*Bh + Ah*Bl + Al*Bh
__device__ __forceinline__ void mma3(float4& d, const uint32_t ah[4],
                                     const uint32_t al[4],
                                     uint32_t bh0, uint32_t bh1,
                                     uint32_t bl0, uint32_t bl1) {
    mma16(d, ah[0], ah[1], ah[2], ah[3], bh0, bh1);
    mma16(d, ah[0], ah[1], ah[2], ah[3], bl0, bl1);
    mma16(d, al[0], al[1], al[2], al[3], bh0, bh1);
}

// ---------------------------------------------------------------------------
// GEMM: compensated fp16, BM=128 BN=128 BK=32, 8 warps (4m x 2n).
// Smem [row][16 kpairs + 4 pad] stride 20 words; ldmatrix fragment loads.
// which: 0=Q, 1=K ([h][b][s][e]), 2=V transposed ([h][b][e][s]), 3=out-proj.
// ---------------------------------------------------------------------------
__global__ __launch_bounds__(256, 2)
void gemm_h2(const float* __restrict__ A,
             const float* __restrict__ B,
             float* __restrict__ Out,
             int which)
{
    __shared__ __align__(16) uint32_t Ah[128 * 20], Al[128 * 20];
    __shared__ __align__(16) uint32_t Bh[128 * 20], Bl[128 * 20];   // [n][kpair]

    const int tid  = threadIdx.x;
    const int lane = tid & 31;
    const int wid  = tid >> 5;
    const int g    = lane >> 2;
    const int qd   = lane & 3;
    const int wm   = wid >> 1;
    const int wn   = wid & 1;
    const int m0   = blockIdx.y * 128;
    const int bx   = blockIdx.x;

    // ldmatrix per-lane address components
    const int arow = (lane & 7) + ((lane >> 3) & 1) * 8;
    const int acol = (lane >> 4) * 4;
    const uint32_t AH = smem_u32(Ah), AL = smem_u32(Al);
    const uint32_t BH = smem_u32(Bh), BL = smem_u32(Bl);
    const uint32_t a_off0 = ((wm * 32 + arow) * 20 + acol) * 4;
    const uint32_t a_off1 = a_off0 + 16 * 20 * 4;
    const uint32_t b_off0 = (wn * 64 + lane) * 20 * 4;
    const uint32_t b_off1 = b_off0 + 32 * 20 * 4;

    float4 acc[2][8];
    #pragma unroll
    for (int i = 0; i < 2; i++)
        #pragma unroll
        for (int j = 0; j < 8; j++) acc[i][j] = make_float4(0.f, 0.f, 0.f, 0.f);

    const int bn4 = (tid & 31) * 4;      // B-load: n col base
    const int bp2 = (tid >> 5) * 2;      // B-load: k-pair base

    for (int k0 = 0; k0 < DMODEL; k0 += 32) {
        // ---- A tile 128x32: 4 float4/thread
        #pragma unroll
        for (int t = 0; t < 4; t++) {
            int f = tid + t * 256;
            int row = f >> 3, c = f & 7;
            float4 a = *(const float4*)(A + (size_t)(m0 + row) * DMODEL + k0 + c * 4);
            uint32_t h0, l0, h1, l1;
            split2(a.x, a.y, h0, l0);
            split2(a.z, a.w, h1, l1);
            int idx = row * 20 + 2 * c;
            *(uint2*)&Ah[idx] = make_uint2(h0, h1);
            *(uint2*)&Al[idx] = make_uint2(l0, l1);
        }
        // ---- B tile -> [n][kpair]: 2 pairs x 4 cols per thread
        #pragma unroll
        for (int pi = 0; pi < 2; pi++) {
            int p = bp2 + pi;
            const float *r0, *r1;
            if (which < 3) {
                int head = bx * 2 + (bn4 >= 64);
                int col  = bn4 & 63;
                r0 = B + ((size_t)head * DMODEL + k0 + 2 * p) * HID + col;
                r1 = r0 + HID;
            } else {
                r0 = B + (size_t)(k0 + 2 * p) * DMODEL + bx * 128 + bn4;
                r1 = r0 + DMODEL;
            }
            float4 v0 = *(const float4*)r0;
            float4 v1 = *(const float4*)r1;
            const float e0[4] = {v0.x, v0.y, v0.z, v0.w};
            const float e1[4] = {v1.x, v1.y, v1.z, v1.w};
            #pragma unroll
            for (int j = 0; j < 4; j++) {
                uint32_t h, l;
                split2(e0[j], e1[j], h, l);
                Bh[(bn4 + j) * 20 + p] = h;
                Bl[(bn4 + j) * 20 + p] = l;
            }
        }
        __syncthreads();

        #pragma unroll
        for (int s = 0; s < 2; s++) {
            uint32_t sc = s * 32;                 // s*8 words in bytes
            uint32_t ah0[4], al0[4], ah1[4], al1[4];
            ldsm_x4(ah0[0], ah0[1], ah0[2], ah0[3], AH + a_off0 + sc);
            ldsm_x4(al0[0], al0[1], al0[2], al0[3], AL + a_off0 + sc);
            ldsm_x4(ah1[0], ah1[1], ah1[2], ah1[3], AH + a_off1 + sc);
            ldsm_x4(al1[0], al1[1], al1[2], al1[3], AL + a_off1 + sc);
            #pragma unroll
            for (int hb = 0; hb < 2; hb++) {
                uint32_t boff = (hb ? b_off1 : b_off0) + sc;
                uint32_t bh0[4], bh1[4], bl0[4], bl1[4];
                ldsm_x4(bh0[0], bh0[1], bh0[2], bh0[3], BH + boff);
                ldsm_x4(bh1[0], bh1[1], bh1[2], bh1[3], BH + boff + 16);
                ldsm_x4(bl0[0], bl0[1], bl0[2], bl0[3], BL + boff);
                ldsm_x4(bl1[0], bl1[1], bl1[2], bl1[3], BL + boff + 16);
                #pragma unroll
                for (int j = 0; j < 4; j++) {
                    int nf = hb * 4 + j;
                    mma3(acc[0][nf], ah0, al0, bh0[j], bh1[j], bl0[j], bl1[j]);
                    mma3(acc[1][nf], ah1, al1, bh0[j], bh1[j], bl0[j], bl1[j]);
                }
            }
        }
        __syncthreads();
    }

    // Epilogue. D frag: (x,y)=row g cols (2qd,2qd+1); (z,w)=row g+8.
    #pragma unroll
    for (int mf = 0; mf < 2; mf++) {
        int mA = m0 + wm * 32 + mf * 16 + g;
        int mB = mA + 8;
        #pragma unroll
        for (int nf = 0; nf < 8; nf++) {
            float4 c = acc[mf][nf];
            if (which < 2) {
                float* O = (which == 0) ? g_Q : g_K;
                int head = bx * 2 + wn;
                int e = nf * 8 + 2 * qd;
                int bA = mA >> 11, sA = mA & 2047;
                int bB = mB >> 11, sB = mB & 2047;
                *(float2*)(O + (((size_t)head * BATCH + bA) * SEQ + sA) * HID + e) =
                    make_float2(c.x, c.y);
                *(float2*)(O + (((size_t)head * BATCH + bB) * SEQ + sB) * HID + e) =
                    make_float2(c.z, c.w);
            } else if (which == 2) {
                int head = bx * 2 + wn;
                int e = nf * 8 + 2 * qd;
                int bA = mA >> 11, sA = mA & 2047;
                int bB = mB >> 11, sB = mB & 2047;
                size_t base = ((size_t)head * BATCH) * HID * SEQ;
                g_Vt[base + ((size_t)bA * HID + e    ) * SEQ + sA] = c.x;
                g_Vt[base + ((size_t)bA * HID + e + 1) * SEQ + sA] = c.y;
                g_Vt[base + ((size_t)bB * HID + e    ) * SEQ + sB] = c.z;
                g_Vt[base + ((size_t)bB * HID + e + 1) * SEQ + sB] = c.w;
            } else {
                int n = bx * 128 + wn * 64 + nf * 8 + 2 * qd;
                *(float2*)(Out + (size_t)mA * DMODEL + n) = make_float2(c.x, c.y);
                *(float2*)(Out + (size_t)mB * DMODEL + n) = make_float2(c.z, c.w);
            }
        }
    }
}

// ---------------------------------------------------------------------------
// Flash attention, compensated fp16 + ldmatrix + P-in-registers.
// BQ=128 (8 warps x 16 rows), K tile 64. Smem stride 36 words.
// Smem: Qh/Ql[128][36], Kh/Kl[64][36], Vh/Vl[64][36] = 73728 B.
// ---------------------------------------------------------------------------
#define ATTN_SMEM 73728

__global__ __launch_bounds__(256, 2)
void attn_h2()
{
    extern __shared__ uint32_t sm[];
    uint32_t* Qh = sm;                 // [128][36]
    uint32_t* Ql = Qh + 128 * 36;
    uint32_t* Kh = Ql + 128 * 36;      // [64][36]   [key][epair]
    uint32_t* Kl = Kh + 64 * 36;
    uint32_t* Vh = Kl + 64 * 36;       // [64][36]   [e][keypair]
    uint32_t* Vl = Vh + 64 * 36;

    const int tid  = threadIdx.x;
    const int lane = tid & 31;
    const int g    = lane >> 2;
    const int qd   = lane & 3;
    const int wq0  = (tid >> 5) * 16;

    const int q0 = blockIdx.x * 128;
    const int h  = blockIdx.y;
    const int b  = blockIdx.z;

    const float* Qg  = g_Q  + ((size_t)h * BATCH + b) * SEQ * HID;
    const float* Kg  = g_K  + ((size_t)h * BATCH + b) * SEQ * HID;
    const float* Vtg = g_Vt + ((size_t)h * BATCH + b) * HID * SEQ;

    // ldmatrix address components
    const int arow = (lane & 7) + ((lane >> 3) & 1) * 8;
    const int acol = (lane >> 4) * 4;
    const uint32_t QH = smem_u32(Qh), QL = smem_u32(Ql);
    const uint32_t KH = smem_u32(Kh), KL = smem_u32(Kl);
    const uint32_t VH = smem_u32(Vh), VL = smem_u32(Vl);
    const uint32_t q_off = ((wq0 + arow) * 36 + acol) * 4;
    const uint32_t r_off0 = lane * 36 * 4;           // B rows 0-31
    const uint32_t r_off1 = r_off0 + 32 * 36 * 4;    // B rows 32-63

    // Load Q tile (scaled): 2048 float4, 8/thread
    #pragma unroll
    for (int t = 0; t < 8; t++) {
        int f = tid + t * 256;
        int row = f >> 4, c = f & 15;
        float4 a = *(const float4*)(Qg + (size_t)(q0 + row) * HID + c * 4);
        uint32_t h0, l0, h1, l1;
        split2(a.x * NORM, a.y * NORM, h0, l0);
        split2(a.z * NORM, a.w * NORM, h1, l1);
        int idx = row * 36 + 2 * c;
        *(uint2*)&Qh[idx] = make_uint2(h0, h1);
        *(uint2*)&Ql[idx] = make_uint2(l0, l1);
    }

    float4 o[8];
    #pragma unroll
    for (int j = 0; j < 8; j++) o[j] = make_float4(0.f, 0.f, 0.f, 0.f);
    float mA = -1e30f, mB = -1e30f, lA = 0.f, lB = 0.f;

    for (int kt = 0; kt < SEQ / 64; kt++) {
        const int k0 = kt * 64;
        __syncthreads();   // prev iter done reading K/V
        #pragma unroll
        for (int t = 0; t < 4; t++) {
            int f = tid + t * 256;
            int row = f >> 4, c = f & 15;
            int idx = row * 36 + 2 * c;
            float4 kv = *(const float4*)(Kg + (size_t)(k0 + row) * HID + c * 4);
            uint32_t h0, l0, h1, l1;
            split2(kv.x, kv.y, h0, l0);
            split2(kv.z, kv.w, h1, l1);
            *(uint2*)&Kh[idx] = make_uint2(h0, h1);
            *(uint2*)&Kl[idx] = make_uint2(l0, l1);
            float4 vv = *(const float4*)(Vtg + (size_t)row * SEQ + k0 + c * 4);
            split2(vv.x, vv.y, h0, l0);
            split2(vv.z, vv.w, h1, l1);
            *(uint2*)&Vh[idx] = make_uint2(h0, h1);
            *(uint2*)&Vl[idx] = make_uint2(l0, l1);
        }
        __syncthreads();

        // ---- S = Q K^T : 4 k16 steps over e=64
        float4 s[8];
        #pragma unroll
        for (int j = 0; j < 8; j++) s[j] = make_float4(0.f, 0.f, 0.f, 0.f);

        #pragma unroll
        for (int st = 0; st < 4; st++) {
            uint32_t sc = st * 32;
            uint32_t ah[4], al[4];
            ldsm_x4(ah[0], ah[1], ah[2], ah[3], QH + q_off + sc);
            ldsm_x4(al[0], al[1], al[2], al[3], QL + q_off + sc);
            #pragma unroll
            for (int hb = 0; hb < 2; hb++) {
                uint32_t boff = (hb ? r_off1 : r_off0) + sc;
                uint32_t bh0[4], bh1[4], bl0[4], bl1[4];
                ldsm_x4(bh0[0], bh0[1], bh0[2], bh0[3], KH + boff);
                ldsm_x4(bh1[0], bh1[1], bh1[2], bh1[3], KH + boff + 16);
                ldsm_x4(bl0[0], bl0[1], bl0[2], bl0[3], KL + boff);
                ldsm_x4(bl1[0], bl1[1], bl1[2], bl1[3], KL + boff + 16);
                #pragma unroll
                for (int j = 0; j < 4; j++)
                    mma3(s[hb * 4 + j], ah, al, bh0[j], bh1[j], bl0[j], bl1[j]);
            }
        }

        // ---- online softmax. (x,y): row g; (z,w): row g+8
        float mtA = -1e30f, mtB = -1e30f;
        #pragma unroll
        for (int nf = 0; nf < 8; nf++) {
            mtA = fmaxf(mtA, fmaxf(s[nf].x, s[nf].y));
            mtB = fmaxf(mtB, fmaxf(s[nf].z, s[nf].w));
        }
        mtA = fmaxf(mtA, __shfl_xor_sync(0xffffffffu, mtA, 1));
        mtA = fmaxf(mtA, __shfl_xor_sync(0xffffffffu, mtA, 2));
        mtB = fmaxf(mtB, __shfl_xor_sync(0xffffffffu, mtB, 1));
        mtB = fmaxf(mtB, __shfl_xor_sync(0xffffffffu, mtB, 2));

        float mnA = fmaxf(mA, mtA), mnB = fmaxf(mB, mtB);
        float alA = __expf(mA - mnA), alB = __expf(mB - mnB);
        float sumA = 0.f, sumB = 0.f;
        #pragma unroll
        for (int nf = 0; nf < 8; nf++) {
            s[nf].x = __expf(s[nf].x - mnA);
            s[nf].y = __expf(s[nf].y - mnA);
            s[nf].z = __expf(s[nf].z - mnB);
            s[nf].w = __expf(s[nf].w - mnB);
            sumA += s[nf].x + s[nf].y;
            sumB += s[nf].z + s[nf].w;
        }
        sumA += __shfl_xor_sync(0xffffffffu, sumA, 1);
        sumA += __shfl_xor_sync(0xffffffffu, sumA, 2);
        sumB += __shfl_xor_sync(0xffffffffu, sumB, 1);
        sumB += __shfl_xor_sync(0xffffffffu, sumB, 2);
        lA = lA * alA + sumA; mA = mnA;
        lB = lB * alB + sumB; mB = mnB;
        #pragma unroll
        for (int nf = 0; nf < 8; nf++) {
            o[nf].x *= alA; o[nf].y *= alA;
            o[nf].z *= alB; o[nf].w *= alB;
        }

        // ---- O += P V : P comes straight from registers.
        // QK^T C-frag (row g: cols nf*8+2qd,+1) == PV A-frag: for k16 step st,
        // a0/a1 = s[2st].(xy/zw), a2/a3 = s[2st+1].(xy/zw).
        #pragma unroll
        for (int st = 0; st < 4; st++) {
            uint32_t ah[4], al[4];
            split2(s[2 * st].x,     s[2 * st].y,     ah[0], al[0]);
            split2(s[2 * st].z,     s[2 * st].w,     ah[1], al[1]);
            split2(s[2 * st + 1].x, s[2 * st + 1].y, ah[2], al[2]);
            split2(s[2 * st + 1].z, s[2 * st + 1].w, ah[3], al[3]);
            uint32_t sc = st * 32;
            #pragma unroll
            for (int hb = 0; hb < 2; hb++) {
                uint32_t boff = (hb ? r_off1 : r_off0) + sc;
                uint32_t bh0[4], bh1[4], bl0[4], bl1[4];
                ldsm_x4(bh0[0], bh0[1], bh0[2], bh0[3], VH + boff);
                ldsm_x4(bh1[0], bh1[1], bh1[2], bh1[3], VH + boff + 16);
                ldsm_x4(bl0[0], bl0[1], bl0[2], bl0[3], VL + boff);
                ldsm_x4(bl1[0], bl1[1], bl1[2], bl1[3], VL + boff + 16);
                #pragma unroll
                for (int j = 0; j < 4; j++)
                    mma3(o[hb * 4 + j], ah, al, bh0[j], bh1[j], bl0[j], bl1[j]);
            }
        }
    }

    // Normalize, write heads: g_Hd[b][q][h*64+e]
    float invA = 1.f / lA, invB = 1.f / lB;
    int qA = q0 + wq0 + g, qB = qA + 8;
    #pragma unroll
    for (int nf = 0; nf < 8; nf++) {
        int e = nf * 8 + 2 * qd;
        *(float2*)(g_Hd + ((size_t)b * SEQ + qA) * DMODEL + h * HID + e) =
            make_float2(o[nf].x * invA, o[nf].y * invA);
        *(float2*)(g_Hd + ((size_t)b * SEQ + qB) * DMODEL + h * HID + e) =
            make_float2(o[nf].z * invB, o[nf].w * invB);
    }
}

// ---------------------------------------------------------------------------
extern "C" void kernel_launch(void* const* d_in, const int* in_sizes, int n_in,
                              void* d_out, int out_size)
{
    const float* q  = (const float*)d_in[0];
    const float* k  = (const float*)d_in[1];
    const float* v  = (const float*)d_in[2];
    const float* Wq = (const float*)d_in[3];
    const float* Wk = (const float*)d_in[4];
    const float* Wv = (const float*)d_in[5];
    const float* Wo = (const float*)d_in[6];
    float* out = (float*)d_out;

    cudaFuncSetAttribute(attn_h2,
        cudaFuncAttributeMaxDynamicSharedMemorySize, ATTN_SMEM);

    float* hd_ptr;
    cudaGetSymbolAddress((void**)&hd_ptr, g_Hd);

    dim3 gproj(DMODEL / 128, MROWS / 128);   // (8, 32)
    gemm_h2<<<gproj, 256>>>(q, Wq, nullptr, 0);
    gemm_h2<<<gproj, 256>>>(k, Wk, nullptr, 1);
    gemm_h2<<<gproj, 256>>>(v, Wv, nullptr, 2);

    attn_h2<<<dim3(SEQ / 128, NHEADS, BATCH), 256, ATTN_SMEM>>>();

    gemm_h2<<<gproj, 256>>>(hd_ptr, Wo, out, 3);
}

// round 7
// speedup vs baseline: 2.6962x; 1.0791x over previous
#include <cuda_runtime.h>
#include <cuda_fp16.h>
#include <stdint.h>

#define NHEADS 16
#define BATCH  2
#define SEQ    2048
#define DMODEL 1024
#define HID    64
#define MROWS  4096
#define KPAIRS 512          // DMODEL/2
#define NORM   0.125f

// ---------------------------------------------------------------------------
// Global scratch (pre-split fp16 hi/lo half2-pair arrays)
// ---------------------------------------------------------------------------
__device__ uint32_t g_Xh[3u*MROWS*KPAIRS], g_Xl[3u*MROWS*KPAIRS];   // inputs  [which][m][kpair]
__device__ uint32_t g_Wh[4u*DMODEL*KPAIRS], g_Wl[4u*DMODEL*KPAIRS]; // weights [which][n][kpair] (n-major)
__device__ uint32_t g_Qh[MROWS*KPAIRS], g_Ql[MROWS*KPAIRS];         // [h][b][s][32 epairs]
__device__ uint32_t g_Kh[MROWS*KPAIRS], g_Kl[MROWS*KPAIRS];
__device__ uint32_t g_Vh[MROWS*KPAIRS], g_Vl[MROWS*KPAIRS];
__device__ uint32_t g_Hh[MROWS*KPAIRS], g_Hl[MROWS*KPAIRS];         // attn out [b][s][512 pairs]

// ---------------------------------------------------------------------------
// helpers
// ---------------------------------------------------------------------------
__device__ __forceinline__ void split2(float x, float y, uint32_t& hi, uint32_t& lo) {
    __half hx = __float2half_rn(x), hy = __float2half_rn(y);
    __half2 H = __halves2half2(hx, hy);
    __half2 L = __floats2half2_rn(x - __half2float(hx), y - __half2float(hy));
    hi = *reinterpret_cast<uint32_t*>(&H);
    lo = *reinterpret_cast<uint32_t*>(&L);
}
__device__ __forceinline__ uint32_t smem_u32(const void* p) {
    return (uint32_t)__cvta_generic_to_shared(p);
}
__device__ __forceinline__ void ldsm_x4(uint32_t* r, uint32_t addr) {
    asm volatile("ldmatrix.sync.aligned.m8n8.x4.shared.b16 {%0,%1,%2,%3},[%4];"
        : "=r"(r[0]), "=r"(r[1]), "=r"(r[2]), "=r"(r[3]) : "r"(addr));
}
__device__ __forceinline__ void ldsm_x4t(uint32_t* r, uint32_t addr) {
    asm volatile("ldmatrix.sync.aligned.m8n8.x4.trans.shared.b16 {%0,%1,%2,%3},[%4];"
        : "=r"(r[0]), "=r"(r[1]), "=r"(r[2]), "=r"(r[3]) : "r"(addr));
}
__device__ __forceinline__ void mma16(float4& d, const uint32_t* a,
                                      uint32_t b0, uint32_t b1) {
    asm volatile(
        "mma.sync.aligned.m16n8k16.row.col.f32.f16.f16.f32 "
        "{%0,%1,%2,%3},{%4,%5,%6,%7},{%8,%9},{%0,%1,%2,%3};"
        : "+f"(d.x), "+f"(d.y), "+f"(d.z), "+f"(d.w)
        : "r"(a[0]), "r"(a[1]), "r"(a[2]), "r"(a[3]), "r"(b0), "r"(b1));
}
__device__ __forceinline__ void cp16(uint32_t dst, const void* src) {
    asm volatile("cp.async.cg.shared.global [%0], [%1], 16;" :: "r"(dst), "l"(src));
}
#define CP_COMMIT() asm volatile("cp.async.commit_group;")
#define CP_WAIT(N)  asm volatile("cp.async.wait_group %0;" :: "n"(N))

// ---------------------------------------------------------------------------
// presplit kernels
// ---------------------------------------------------------------------------
__global__ void presplit_pairs(const float* __restrict__ src,
                               uint32_t* __restrict__ dh, uint32_t* __restrict__ dl,
                               int npairs) {
    int i = blockIdx.x * 256 + threadIdx.x;
    if (i < npairs) {
        float2 v = ((const float2*)src)[i];
        uint32_t h, l; split2(v.x, v.y, h, l);
        dh[i] = h; dl[i] = l;
    }
}
// W [16][1024][64] -> [n=h*64+e][kpair], scaled
__global__ void presplit_wqkv(const float* __restrict__ W,
                              uint32_t* __restrict__ dh, uint32_t* __restrict__ dl,
                              float scale) {
    int i = blockIdx.x * 256 + threadIdx.x;   // over 1024*512
    int n = i >> 9, p = i & 511;
    int h = n >> 6, e = n & 63;
    const float* s = W + (size_t)h * DMODEL * HID + (size_t)(2 * p) * HID + e;
    uint32_t hh, ll; split2(s[0] * scale, s[HID] * scale, hh, ll);
    dh[i] = hh; dl[i] = ll;
}
// Wo flat [1024][1024] (k-major) -> [n][kpair]
__global__ void presplit_wo(const float* __restrict__ W,
                            uint32_t* __restrict__ dh, uint32_t* __restrict__ dl) {
    int i = blockIdx.x * 256 + threadIdx.x;
    int n = i >> 9, p = i & 511;
    uint32_t hh, ll;
    split2(W[(size_t)(2 * p) * DMODEL + n], W[(size_t)(2 * p + 1) * DMODEL + n], hh, ll);
    dh[i] = hh; dl[i] = ll;
}

// ---------------------------------------------------------------------------
// GEMM, pure pre-split fp16: C[m][n] += A·B^T, A [M][kpair], B [N][kpair].
// BM=BN=128, BK=32 (16 pairs), 8 warps (4m x 2n). cp.async double-buffered.
// Smem per buffer: Ah/Al/Bh/Bl [128][20] (stride 20 words, ldsm-conflict-free).
// which 0/1/2: epilogue splits and writes Q/K/V pair arrays; 3: fp32 to Outf.
// ---------------------------------------------------------------------------
__global__ __launch_bounds__(256, 2)
void gemm_p(const uint32_t* __restrict__ Ah, const uint32_t* __restrict__ Al,
            const uint32_t* __restrict__ Bh, const uint32_t* __restrict__ Bl,
            uint32_t* __restrict__ Oh, uint32_t* __restrict__ Ol,
            float* __restrict__ Outf, int which)
{
    extern __shared__ uint32_t sg[];   // [2][4][2560]

    const int tid  = threadIdx.x;
    const int lane = tid & 31;
    const int wid  = tid >> 5;
    const int g    = lane >> 2;
    const int qd   = lane & 3;
    const int wm   = wid >> 1;
    const int wn   = wid & 1;
    const int m0   = blockIdx.y * 128;
    const int n0   = blockIdx.x * 128;

    const uint32_t SB = smem_u32(sg);
    const int arow = lane & 15, acol = (lane >> 4) * 4;
    const uint32_t a_off0 = ((wm * 32 + arow) * 20 + acol) * 4;
    const uint32_t a_off1 = a_off0 + 16 * 20 * 4;
    const uint32_t b_off0 = ((wn * 64 + lane) * 20) * 4;
    const uint32_t b_off1 = b_off0 + 32 * 20 * 4;

    float4 acc[2][8];
    #pragma unroll
    for (int i = 0; i < 2; i++)
        #pragma unroll
        for (int j = 0; j < 8; j++) acc[i][j] = make_float4(0.f, 0.f, 0.f, 0.f);

    auto load_tile = [&](int kt, int bf) {
        const uint32_t base = SB + (uint32_t)bf * 10240 * 4;
        int kp0 = kt * 16;
        #pragma unroll
        for (int t = 0; t < 8; t++) {
            int f = tid + t * 256;            // 0..2047
            int arr = f >> 9, gg = f & 511;
            int row = gg >> 2, ch = gg & 3;
            uint32_t dst = base + (uint32_t)(arr * 2560 + row * 20 + ch * 4) * 4;
            const uint32_t* src =
                (arr == 0) ? Ah + (size_t)(m0 + row) * KPAIRS + kp0 + ch * 4 :
                (arr == 1) ? Al + (size_t)(m0 + row) * KPAIRS + kp0 + ch * 4 :
                (arr == 2) ? Bh + (size_t)(n0 + row) * KPAIRS + kp0 + ch * 4 :
                             Bl + (size_t)(n0 + row) * KPAIRS + kp0 + ch * 4;
            cp16(dst, src);
        }
    };

    load_tile(0, 0);
    CP_COMMIT();

    for (int kt = 0; kt < 32; kt++) {
        if (kt < 31) { load_tile(kt + 1, (kt + 1) & 1); CP_COMMIT(); CP_WAIT(1); }
        else         { CP_WAIT(0); }
        __syncthreads();

        const uint32_t base = SB + (uint32_t)(kt & 1) * 10240 * 4;
        const uint32_t AHB = base, ALB = base + 2560 * 4;
        const uint32_t BHB = base + 5120 * 4, BLB = base + 7680 * 4;

        #pragma unroll
        for (int s = 0; s < 2; s++) {
            uint32_t sc = s * 32;
            uint32_t ah0[4], al0[4], ah1[4], al1[4];
            ldsm_x4(ah0, AHB + a_off0 + sc);
            ldsm_x4(al0, ALB + a_off0 + sc);
            ldsm_x4(ah1, AHB + a_off1 + sc);
            ldsm_x4(al1, ALB + a_off1 + sc);
            #pragma unroll
            for (int hb = 0; hb < 2; hb++) {
                uint32_t boff = (hb ? b_off1 : b_off0) + sc;
                uint32_t bh0[4], bh1[4], bl0[4], bl1[4];
                ldsm_x4(bh0, BHB + boff);
                ldsm_x4(bh1, BHB + boff + 16);
                ldsm_x4(bl0, BLB + boff);
                ldsm_x4(bl1, BLB + boff + 16);
                // term-major: 8 independent MMAs between accumulator reuse
                #pragma unroll
                for (int j = 0; j < 4; j++) mma16(acc[0][hb*4+j], ah0, bh0[j], bh1[j]);
                #pragma unroll
                for (int j = 0; j < 4; j++) mma16(acc[1][hb*4+j], ah1, bh0[j], bh1[j]);
                #pragma unroll
                for (int j = 0; j < 4; j++) mma16(acc[0][hb*4+j], ah0, bl0[j], bl1[j]);
                #pragma unroll
                for (int j = 0; j < 4; j++) mma16(acc[1][hb*4+j], ah1, bl0[j], bl1[j]);
                #pragma unroll
                for (int j = 0; j < 4; j++) mma16(acc[0][hb*4+j], al0, bh0[j], bh1[j]);
                #pragma unroll
                for (int j = 0; j < 4; j++) mma16(acc[1][hb*4+j], al1, bh0[j], bh1[j]);
            }
        }
        __syncthreads();
    }

    // Epilogue
    #pragma unroll
    for (int mf = 0; mf < 2; mf++) {
        int mA = m0 + wm * 32 + mf * 16 + g;
        int mB = mA + 8;
        #pragma unroll
        for (int nf = 0; nf < 8; nf++) {
            float4 c = acc[mf][nf];
            if (which < 3) {
                int head = (n0 >> 6) + wn;
                int pr   = nf * 4 + qd;
                int bA = mA >> 11, sA = mA & 2047;
                int bB = mB >> 11, sB = mB & 2047;
                uint32_t hh, ll;
                split2(c.x, c.y, hh, ll);
                size_t d = (((size_t)head * BATCH + bA) * SEQ + sA) * 32 + pr;
                Oh[d] = hh; Ol[d] = ll;
                split2(c.z, c.w, hh, ll);
                d = (((size_t)head * BATCH + bB) * SEQ + sB) * 32 + pr;
                Oh[d] = hh; Ol[d] = ll;
            } else {
                int n = n0 + wn * 64 + nf * 8 + 2 * qd;
                *(float2*)(Outf + (size_t)mA * DMODEL + n) = make_float2(c.x, c.y);
                *(float2*)(Outf + (size_t)mB * DMODEL + n) = make_float2(c.z, c.w);
            }
        }
    }
}

// ---------------------------------------------------------------------------
// Flash attention, pre-split fp16 + cp.async double-buffered K/V + ldmatrix
// (V via ldmatrix.trans), P in registers, term-interleaved MMAs.
// BQ=128 (8 warps x 16 rows), K tile 64. Smem stride 36 words.
// Layout (words): Qh@0(4608) Ql@4608 | buf b @9216+b*9216: Kh,Kl,Vh,Vl (2304 ea)
// ---------------------------------------------------------------------------
#define ATTN_SMEM ((9216 + 2 * 9216) * 4)   // 110592 B

__global__ __launch_bounds__(256, 2)
void attn_p()
{
    extern __shared__ uint32_t sa[];

    const int tid  = threadIdx.x;
    const int lane = tid & 31;
    const int g    = lane >> 2;
    const int qd   = lane & 3;
    const int wq0  = (tid >> 5) * 16;

    const int q0 = blockIdx.x * 128;
    const int h  = blockIdx.y;
    const int b  = blockIdx.z;
    const size_t base32 = ((size_t)h * BATCH + b) * SEQ * 32;

    const uint32_t SB = smem_u32(sa);
    const uint32_t QH = SB, QL = SB + 4608 * 4;

    const int arow = lane & 15, acol = (lane >> 4) * 4;
    const uint32_t q_off  = ((wq0 + arow) * 36 + acol) * 4;
    const uint32_t r_off0 = (lane * 36) * 4;
    const uint32_t r_off1 = r_off0 + 32 * 36 * 4;
    // V trans per-lane base: row = (lane&7) + ((lane>>3)&1)*8, colw = (lane>>4)*4
    const uint32_t v_off = (((lane & 7) + ((lane >> 3) & 1) * 8) * 36
                            + (lane >> 4) * 4) * 4;

    auto load_q = [&]() {
        #pragma unroll
        for (int t = 0; t < 8; t++) {
            int f = tid + t * 256;              // 0..2047
            int arr = f >> 10, gg = f & 1023;
            int row = gg >> 3, ch = gg & 7;
            uint32_t dst = SB + (uint32_t)((arr ? 4608 : 0) + row * 36 + ch * 4) * 4;
            const uint32_t* src = (arr ? g_Ql : g_Qh)
                + base32 + (size_t)(q0 + row) * 32 + ch * 4;
            cp16(dst, src);
        }
    };
    auto load_kv = [&](int kt, int bf) {
        uint32_t bb = SB + (uint32_t)(9216 + bf * 9216) * 4;
        int k0 = kt * 64;
        #pragma unroll
        for (int t = 0; t < 8; t++) {
            int f = tid + t * 256;              // 0..2047
            int arr = f >> 9, gg = f & 511;
            int row = gg >> 3, ch = gg & 7;
            uint32_t dst = bb + (uint32_t)(arr * 2304 + row * 36 + ch * 4) * 4;
            const uint32_t* p =
                (arr == 0) ? g_Kh : (arr == 1) ? g_Kl : (arr == 2) ? g_Vh : g_Vl;
            cp16(dst, p + base32 + (size_t)(k0 + row) * 32 + ch * 4);
        }
    };

    load_q();
    load_kv(0, 0);
    CP_COMMIT();

    float4 o[8];
    #pragma unroll
    for (int j = 0; j < 8; j++) o[j] = make_float4(0.f, 0.f, 0.f, 0.f);
    float mA = -1e30f, mB = -1e30f, lA = 0.f, lB = 0.f;

    for (int kt = 0; kt < SEQ / 64; kt++) {
        if (kt < 31) { load_kv(kt + 1, (kt + 1) & 1); CP_COMMIT(); CP_WAIT(1); }
        else         { CP_WAIT(0); }
        __syncthreads();

        const uint32_t KB = SB + (uint32_t)(9216 + (kt & 1) * 9216) * 4;
        const uint32_t KH = KB, KL = KB + 2304 * 4;
        const uint32_t VH = KB + 4608 * 4, VL = KB + 6912 * 4;

        // ---- S = Q K^T
        float4 s[8];
        #pragma unroll
        for (int j = 0; j < 8; j++) s[j] = make_float4(0.f, 0.f, 0.f, 0.f);

        #pragma unroll
        for (int st = 0; st < 4; st++) {
            uint32_t sc = st * 32;
            uint32_t ah[4], al[4];
            ldsm_x4(ah, QH + q_off + sc);
            ldsm_x4(al, QL + q_off + sc);
            #pragma unroll
            for (int hb = 0; hb < 2; hb++) {
                uint32_t boff = (hb ? r_off1 : r_off0) + sc;
                uint32_t bh0[4], bh1[4], bl0[4], bl1[4];
                ldsm_x4(bh0, KH + boff);
                ldsm_x4(bh1, KH + boff + 16);
                ldsm_x4(bl0, KL + boff);
                ldsm_x4(bl1, KL + boff + 16);
                #pragma unroll
                for (int j = 0; j < 4; j++) mma16(s[hb*4+j], ah, bh0[j], bh1[j]);
                #pragma unroll
                for (int j = 0; j < 4; j++) mma16(s[hb*4+j], ah, bl0[j], bl1[j]);
                #pragma unroll
                for (int j = 0; j < 4; j++) mma16(s[hb*4+j], al, bh0[j], bh1[j]);
            }
        }

        // ---- online softmax. (x,y): row g; (z,w): row g+8
        float mtA = -1e30f, mtB = -1e30f;
        #pragma unroll
        for (int nf = 0; nf < 8; nf++) {
            mtA = fmaxf(mtA, fmaxf(s[nf].x, s[nf].y));
            mtB = fmaxf(mtB, fmaxf(s[nf].z, s[nf].w));
        }
        mtA = fmaxf(mtA, __shfl_xor_sync(0xffffffffu, mtA, 1));
        mtA = fmaxf(mtA, __shfl_xor_sync(0xffffffffu, mtA, 2));
        mtB = fmaxf(mtB, __shfl_xor_sync(0xffffffffu, mtB, 1));
        mtB = fmaxf(mtB, __shfl_xor_sync(0xffffffffu, mtB, 2));

        float mnA = fmaxf(mA, mtA), mnB = fmaxf(mB, mtB);
        float alA = __expf(mA - mnA), alB = __expf(mB - mnB);
        float sumA = 0.f, sumB = 0.f;
        #pragma unroll
        for (int nf = 0; nf < 8; nf++) {
            s[nf].x = __expf(s[nf].x - mnA);
            s[nf].y = __expf(s[nf].y - mnA);
            s[nf].z = __expf(s[nf].z - mnB);
            s[nf].w = __expf(s[nf].w - mnB);
            sumA += s[nf].x + s[nf].y;
            sumB += s[nf].z + s[nf].w;
        }
        sumA += __shfl_xor_sync(0xffffffffu, sumA, 1);
        sumA += __shfl_xor_sync(0xffffffffu, sumA, 2);
        sumB += __shfl_xor_sync(0xffffffffu, sumB, 1);
        sumB += __shfl_xor_sync(0xffffffffu, sumB, 2);
        lA = lA * alA + sumA; mA = mnA;
        lB = lB * alB + sumB; mB = mnB;
        #pragma unroll
        for (int nf = 0; nf < 8; nf++) {
            o[nf].x *= alA; o[nf].y *= alA;
            o[nf].z *= alB; o[nf].w *= alB;
        }

        // ---- O += P V (P from registers; V via ldmatrix.trans)
        #pragma unroll
        for (int st = 0; st < 4; st++) {
            uint32_t pah[4], pal[4];
            split2(s[2*st].x,   s[2*st].y,   pah[0], pal[0]);
            split2(s[2*st].z,   s[2*st].w,   pah[1], pal[1]);
            split2(s[2*st+1].x, s[2*st+1].y, pah[2], pal[2]);
            split2(s[2*st+1].z, s[2*st+1].w, pah[3], pal[3]);
            uint32_t stoff = (uint32_t)(st * 16 * 36) * 4;
            #pragma unroll
            for (int egp = 0; egp < 2; egp++) {
                uint32_t e0 = (uint32_t)(egp * 2) * 32;      // eg*8 words in bytes
                uint32_t vh0[4], vh1[4], vl0[4], vl1[4];
                ldsm_x4t(vh0, VH + v_off + stoff + e0);
                ldsm_x4t(vh1, VH + v_off + stoff + e0 + 32);
                ldsm_x4t(vl0, VL + v_off + stoff + e0);
                ldsm_x4t(vl1, VL + v_off + stoff + e0 + 32);
                int nb = egp * 4;
                // vh0: (b0,b1) for nf=nb, (b0,b1) for nf=nb+1; vh1: nb+2, nb+3
                mma16(o[nb+0], pah, vh0[0], vh0[1]);
                mma16(o[nb+1], pah, vh0[2], vh0[3]);
                mma16(o[nb+2], pah, vh1[0], vh1[1]);
                mma16(o[nb+3], pah, vh1[2], vh1[3]);
                mma16(o[nb+0], pah, vl0[0], vl0[1]);
                mma16(o[nb+1], pah, vl0[2], vl0[3]);
                mma16(o[nb+2], pah, vl1[0], vl1[1]);
                mma16(o[nb+3], pah, vl1[2], vl1[3]);
                mma16(o[nb+0], pal, vh0[0], vh0[1]);
                mma16(o[nb+1], pal, vh0[2], vh0[3]);
                mma16(o[nb+2], pal, vh1[0], vh1[1]);
                mma16(o[nb+3], pal, vh1[2], vh1[3]);
            }
        }
        __syncthreads();
    }

    // Normalize; write split pairs to g_Hh/g_Hl [b*SEQ+q][h*32 + nf*4+qd]
    float invA = 1.f / lA, invB = 1.f / lB;
    int qA = q0 + wq0 + g, qB = qA + 8;
    #pragma unroll
    for (int nf = 0; nf < 8; nf++) {
        uint32_t hh, ll;
        int pr = h * 32 + nf * 4 + qd;
        split2(o[nf].x * invA, o[nf].y * invA, hh, ll);
        g_Hh[((size_t)b * SEQ + qA) * KPAIRS + pr] = hh;
        g_Hl[((size_t)b * SEQ + qA) * KPAIRS + pr] = ll;
        split2(o[nf].z * invB, o[nf].w * invB, hh, ll);
        g_Hh[((size_t)b * SEQ + qB) * KPAIRS + pr] = hh;
        g_Hl[((size_t)b * SEQ + qB) * KPAIRS + pr] = ll;
    }
}

// ---------------------------------------------------------------------------
extern "C" void kernel_launch(void* const* d_in, const int* in_sizes, int n_in,
                              void* d_out, int out_size)
{
    const float* q  = (const float*)d_in[0];
    const float* k  = (const float*)d_in[1];
    const float* v  = (const float*)d_in[2];
    const float* Wq = (const float*)d_in[3];
    const float* Wk = (const float*)d_in[4];
    const float* Wv = (const float*)d_in[5];
    const float* Wo = (const float*)d_in[6];
    float* out = (float*)d_out;

    cudaFuncSetAttribute(gemm_p, cudaFuncAttributeMaxDynamicSharedMemorySize, 81920);
    cudaFuncSetAttribute(attn_p, cudaFuncAttributeMaxDynamicSharedMemorySize, ATTN_SMEM);

    uint32_t *xh, *xl, *wh, *wl, *qh, *ql, *kh, *kl, *vh, *vl, *hh, *hl;
    cudaGetSymbolAddress((void**)&xh, g_Xh);
    cudaGetSymbolAddress((void**)&xl, g_Xl);
    cudaGetSymbolAddress((void**)&wh, g_Wh);
    cudaGetSymbolAddress((void**)&wl, g_Wl);
    cudaGetSymbolAddress((void**)&qh, g_Qh);
    cudaGetSymbolAddress((void**)&ql, g_Ql);
    cudaGetSymbolAddress((void**)&kh, g_Kh);
    cudaGetSymbolAddress((void**)&kl, g_Kl);
    cudaGetSymbolAddress((void**)&vh, g_Vh);
    cudaGetSymbolAddress((void**)&vl, g_Vl);
    cudaGetSymbolAddress((void**)&hh, g_Hh);
    cudaGetSymbolAddress((void**)&hl, g_Hl);

    const int NP = MROWS * KPAIRS;             // 2097152 pairs per input
    const int WN = DMODEL * KPAIRS;            // 524288 per weight slice

    presplit_pairs<<<NP / 256, 256>>>(q, xh,          xl,          NP);
    presplit_pairs<<<NP / 256, 256>>>(k, xh + NP,     xl + NP,     NP);
    presplit_pairs<<<NP / 256, 256>>>(v, xh + 2 * NP, xl + 2 * NP, NP);
    presplit_wqkv <<<WN / 256, 256>>>(Wq, wh,          wl,          NORM);
    presplit_wqkv <<<WN / 256, 256>>>(Wk, wh + WN,     wl + WN,     1.0f);
    presplit_wqkv <<<WN / 256, 256>>>(Wv, wh + 2 * WN, wl + 2 * WN, 1.0f);
    presplit_wo   <<<WN / 256, 256>>>(Wo, wh + 3 * WN, wl + 3 * WN);

    dim3 gg(DMODEL / 128, MROWS / 128);        // (8, 32)
    gemm_p<<<gg, 256, 81920>>>(xh,          xl,          wh,          wl,
                               qh, ql, nullptr, 0);
    gemm_p<<<gg, 256, 81920>>>(xh + NP,     xl + NP,     wh + WN,     wl + WN,
                               kh, kl, nullptr, 1);
    gemm_p<<<gg, 256, 81920>>>(xh + 2 * NP, xl + 2 * NP, wh + 2 * WN, wl + 2 * WN,
                               vh, vl, nullptr, 2);

    attn_p<<<dim3(SEQ / 128, NHEADS, BATCH), 256, ATTN_SMEM>>>();

    gemm_p<<<gg, 256, 81920>>>(hh, hl, wh + 3 * WN, wl + 3 * WN,
                               nullptr, nullptr, out, 3);
}

// round 9
// speedup vs baseline: 3.0623x; 1.1358x over previous
#include <cuda_runtime.h>
#include <cuda_fp16.h>
#include <stdint.h>

#define NHEADS 16
#define BATCH  2
#define SEQ    2048
#define DMODEL 1024
#define HID    64
#define MROWS  4096
#define KPAIRS 512          // DMODEL/2
#define NORM   0.125f
#define NP     (MROWS*KPAIRS)
#define WN     (DMODEL*KPAIRS)

// ---------------------------------------------------------------------------
// Global scratch (pre-split fp16 hi/lo half2-pair arrays)
// ---------------------------------------------------------------------------
__device__ uint32_t g_Xh[3u*NP], g_Xl[3u*NP];     // inputs  [which][m][kpair]
__device__ uint32_t g_Wh[4u*WN], g_Wl[4u*WN];     // weights [which][n][kpair]
__device__ uint32_t g_Qh[NP], g_Ql[NP];           // [h][b][s][32 epairs]
__device__ uint32_t g_Kh[NP], g_Kl[NP];
__device__ uint32_t g_Vh[NP], g_Vl[NP];
__device__ uint32_t g_Hh[NP], g_Hl[NP];           // attn out [b][s][512 pairs]

// ---------------------------------------------------------------------------
// helpers
// ---------------------------------------------------------------------------
__device__ __forceinline__ void split2(float x, float y, uint32_t& hi, uint32_t& lo) {
    __half hx = __float2half_rn(x), hy = __float2half_rn(y);
    __half2 H = __halves2half2(hx, hy);
    __half2 L = __floats2half2_rn(x - __half2float(hx), y - __half2float(hy));
    hi = *reinterpret_cast<uint32_t*>(&H);
    lo = *reinterpret_cast<uint32_t*>(&L);
}
__device__ __forceinline__ uint32_t pack2(float x, float y) {
    __half2 H = __floats2half2_rn(x, y);
    return *reinterpret_cast<uint32_t*>(&H);
}
__device__ __forceinline__ uint32_t smem_u32(const void* p) {
    return (uint32_t)__cvta_generic_to_shared(p);
}
__device__ __forceinline__ void ldsm_x4(uint32_t* r, uint32_t addr) {
    asm volatile("ldmatrix.sync.aligned.m8n8.x4.shared.b16 {%0,%1,%2,%3},[%4];"
        : "=r"(r[0]), "=r"(r[1]), "=r"(r[2]), "=r"(r[3]) : "r"(addr));
}
__device__ __forceinline__ void ldsm_x4t(uint32_t* r, uint32_t addr) {
    asm volatile("ldmatrix.sync.aligned.m8n8.x4.trans.shared.b16 {%0,%1,%2,%3},[%4];"
        : "=r"(r[0]), "=r"(r[1]), "=r"(r[2]), "=r"(r[3]) : "r"(addr));
}
__device__ __forceinline__ void mma16(float4& d, const uint32_t* a,
                                      uint32_t b0, uint32_t b1) {
    asm volatile(
        "mma.sync.aligned.m16n8k16.row.col.f32.f16.f16.f32 "
        "{%0,%1,%2,%3},{%4,%5,%6,%7},{%8,%9},{%0,%1,%2,%3};"
        : "+f"(d.x), "+f"(d.y), "+f"(d.z), "+f"(d.w)
        : "r"(a[0]), "r"(a[1]), "r"(a[2]), "r"(a[3]), "r"(b0), "r"(b1));
}
__device__ __forceinline__ void cp16(uint32_t dst, const void* src) {
    asm volatile("cp.async.cg.shared.global [%0], [%1], 16;" :: "r"(dst), "l"(src));
}
#define CP_COMMIT() asm volatile("cp.async.commit_group;")
#define CP_WAIT(N)  asm volatile("cp.async.wait_group %0;" :: "n"(N))

// ---------------------------------------------------------------------------
// presplit kernels (z-merged)
// ---------------------------------------------------------------------------
__global__ void presplit_pairs3(const float* __restrict__ s0,
                                const float* __restrict__ s1,
                                const float* __restrict__ s2) {
    int z = blockIdx.z;
    const float* src = (z == 0) ? s0 : (z == 1) ? s1 : s2;
    int i = blockIdx.x * 256 + threadIdx.x;
    float2 v = ((const float2*)src)[i];
    uint32_t h, l; split2(v.x, v.y, h, l);
    g_Xh[(size_t)z * NP + i] = h;
    g_Xl[(size_t)z * NP + i] = l;
}
__global__ void presplit_wqkv3(const float* __restrict__ W0,
                               const float* __restrict__ W1,
                               const float* __restrict__ W2) {
    int z = blockIdx.z;
    const float* W = (z == 0) ? W0 : (z == 1) ? W1 : W2;
    float scale = (z == 0) ? NORM : 1.0f;
    int i = blockIdx.x * 256 + threadIdx.x;
    int n = i >> 9, p = i & 511;
    int h = n >> 6, e = n & 63;
    const float* s = W + (size_t)h * DMODEL * HID + (size_t)(2 * p) * HID + e;
    uint32_t hh, ll; split2(s[0] * scale, s[HID] * scale, hh, ll);
    g_Wh[(size_t)z * WN + i] = hh;
    g_Wl[(size_t)z * WN + i] = ll;
}
__global__ void presplit_wo(const float* __restrict__ W) {
    int i = blockIdx.x * 256 + threadIdx.x;
    int n = i >> 9, p = i & 511;
    uint32_t hh, ll;
    split2(W[(size_t)(2 * p) * DMODEL + n], W[(size_t)(2 * p + 1) * DMODEL + n], hh, ll);
    g_Wh[3u * WN + i] = hh;
    g_Wl[3u * WN + i] = ll;
}

// ---------------------------------------------------------------------------
// QKV projection GEMM (merged z=0,1,2), compensated fp16 (3-term).
// BM=BN=128, BK=32 (16 pairs), 8 warps (4m x 2n). cp.async double-buffered.
// Smem/buffer: Ah/Al/Bh/Bl [128][20] (stride 20 words, ldsm-conflict-free).
// ---------------------------------------------------------------------------
__global__ __launch_bounds__(256, 2)
void gemm_qkv()
{
    extern __shared__ uint32_t sg[];   // [2][4][2560]

    const int z    = blockIdx.z;
    const int tid  = threadIdx.x;
    const int lane = tid & 31;
    const int wid  = tid >> 5;
    const int g    = lane >> 2;
    const int qd   = lane & 3;
    const int wm   = wid >> 1;
    const int wn   = wid & 1;
    const int m0   = blockIdx.y * 128;
    const int n0   = blockIdx.x * 128;

    const uint32_t* Ahg = g_Xh + (size_t)z * NP;
    const uint32_t* Alg = g_Xl + (size_t)z * NP;
    const uint32_t* Bhg = g_Wh + (size_t)z * WN;
    const uint32_t* Blg = g_Wl + (size_t)z * WN;
    uint32_t* Oh = (z == 0) ? g_Qh : (z == 1) ? g_Kh : g_Vh;
    uint32_t* Ol = (z == 0) ? g_Ql : (z == 1) ? g_Kl : g_Vl;

    const uint32_t SB = smem_u32(sg);
    const int arow = lane & 15, acol = (lane >> 4) * 4;
    const uint32_t a_off0 = ((wm * 32 + arow) * 20 + acol) * 4;
    const uint32_t a_off1 = a_off0 + 16 * 20 * 4;
    const uint32_t b_off0 = ((wn * 64 + lane) * 20) * 4;
    const uint32_t b_off1 = b_off0 + 32 * 20 * 4;

    float4 acc[2][8];
    #pragma unroll
    for (int i = 0; i < 2; i++)
        #pragma unroll
        for (int j = 0; j < 8; j++) acc[i][j] = make_float4(0.f, 0.f, 0.f, 0.f);

    auto load_tile = [&](int kt, int bf) {
        const uint32_t base = SB + (uint32_t)bf * 10240 * 4;
        int kp0 = kt * 16;
        #pragma unroll
        for (int t = 0; t < 8; t++) {
            int f = tid + t * 256;
            int arr = f >> 9, gg = f & 511;
            int row = gg >> 2, ch = gg & 3;
            uint32_t dst = base + (uint32_t)(arr * 2560 + row * 20 + ch * 4) * 4;
            const uint32_t* src =
                (arr == 0) ? Ahg + (size_t)(m0 + row) * KPAIRS + kp0 + ch * 4 :
                (arr == 1) ? Alg + (size_t)(m0 + row) * KPAIRS + kp0 + ch * 4 :
                (arr == 2) ? Bhg + (size_t)(n0 + row) * KPAIRS + kp0 + ch * 4 :
                             Blg + (size_t)(n0 + row) * KPAIRS + kp0 + ch * 4;
            cp16(dst, src);
        }
    };

    load_tile(0, 0);
    CP_COMMIT();

    for (int kt = 0; kt < 32; kt++) {
        if (kt < 31) { load_tile(kt + 1, (kt + 1) & 1); CP_COMMIT(); CP_WAIT(1); }
        else         { CP_WAIT(0); }
        __syncthreads();

        const uint32_t base = SB + (uint32_t)(kt & 1) * 10240 * 4;
        const uint32_t AHB = base, ALB = base + 2560 * 4;
        const uint32_t BHB = base + 5120 * 4, BLB = base + 7680 * 4;

        #pragma unroll
        for (int s = 0; s < 2; s++) {
            uint32_t sc = s * 32;
            uint32_t ah0[4], al0[4], ah1[4], al1[4];
            ldsm_x4(ah0, AHB + a_off0 + sc);
            ldsm_x4(al0, ALB + a_off0 + sc);
            ldsm_x4(ah1, AHB + a_off1 + sc);
            ldsm_x4(al1, ALB + a_off1 + sc);
            #pragma unroll
            for (int hb = 0; hb < 2; hb++) {
                uint32_t boff = (hb ? b_off1 : b_off0) + sc;
                uint32_t bh0[4], bh1[4], bl0[4], bl1[4];
                ldsm_x4(bh0, BHB + boff);
                ldsm_x4(bh1, BHB + boff + 16);
                ldsm_x4(bl0, BLB + boff);
                ldsm_x4(bl1, BLB + boff + 16);
                #pragma unroll
                for (int j = 0; j < 4; j++) mma16(acc[0][hb*4+j], ah0, bh0[j], bh1[j]);
                #pragma unroll
                for (int j = 0; j < 4; j++) mma16(acc[1][hb*4+j], ah1, bh0[j], bh1[j]);
                #pragma unroll
                for (int j = 0; j < 4; j++) mma16(acc[0][hb*4+j], ah0, bl0[j], bl1[j]);
                #pragma unroll
                for (int j = 0; j < 4; j++) mma16(acc[1][hb*4+j], ah1, bl0[j], bl1[j]);
                #pragma unroll
                for (int j = 0; j < 4; j++) mma16(acc[0][hb*4+j], al0, bh0[j], bh1[j]);
                #pragma unroll
                for (int j = 0; j < 4; j++) mma16(acc[1][hb*4+j], al1, bh0[j], bh1[j]);
            }
        }
        __syncthreads();
    }

    // Epilogue: split and store Q/K/V pair arrays
    #pragma unroll
    for (int mf = 0; mf < 2; mf++) {
        int mA = m0 + wm * 32 + mf * 16 + g;
        int mB = mA + 8;
        #pragma unroll
        for (int nf = 0; nf < 8; nf++) {
            float4 c = acc[mf][nf];
            int head = (n0 >> 6) + wn;
            int pr   = nf * 4 + qd;
            int bA = mA >> 11, sA = mA & 2047;
            int bB = mB >> 11, sB = mB & 2047;
            uint32_t hh, ll;
            split2(c.x, c.y, hh, ll);
            size_t d = (((size_t)head * BATCH + bA) * SEQ + sA) * 32 + pr;
            Oh[d] = hh; Ol[d] = ll;
            split2(c.z, c.w, hh, ll);
            d = (((size_t)head * BATCH + bB) * SEQ + sB) * 32 + pr;
            Oh[d] = hh; Ol[d] = ll;
        }
    }
}

// ---------------------------------------------------------------------------
// Output projection GEMM: 2-term (Ah·Bh + Ah·Bl), A = g_Hh only (no lo).
// ---------------------------------------------------------------------------
__global__ __launch_bounds__(256, 2)
void gemm_out(float* __restrict__ Outf)
{
    extern __shared__ uint32_t sg[];   // [2][3][2560]

    const int tid  = threadIdx.x;
    const int lane = tid & 31;
    const int wid  = tid >> 5;
    const int g    = lane >> 2;
    const int qd   = lane & 3;
    const int wm   = wid >> 1;
    const int wn   = wid & 1;
    const int m0   = blockIdx.y * 128;
    const int n0   = blockIdx.x * 128;

    const uint32_t* Ahg = g_Hh;
    const uint32_t* Bhg = g_Wh + 3u * WN;
    const uint32_t* Blg = g_Wl + 3u * WN;

    const uint32_t SB = smem_u32(sg);
    const int arow = lane & 15, acol = (lane >> 4) * 4;
    const uint32_t a_off0 = ((wm * 32 + arow) * 20 + acol) * 4;
    const uint32_t a_off1 = a_off0 + 16 * 20 * 4;
    const uint32_t b_off0 = ((wn * 64 + lane) * 20) * 4;
    const uint32_t b_off1 = b_off0 + 32 * 20 * 4;

    float4 acc[2][8];
    #pragma unroll
    for (int i = 0; i < 2; i++)
        #pragma unroll
        for (int j = 0; j < 8; j++) acc[i][j] = make_float4(0.f, 0.f, 0.f, 0.f);

    // per-buffer: Ah @0, Bh @2560, Bl @5120 (words); buffer stride 7680 words
    auto load_tile = [&](int kt, int bf) {
        const uint32_t base = SB + (uint32_t)bf * 7680 * 4;
        int kp0 = kt * 16;
        #pragma unroll
        for (int t = 0; t < 6; t++) {
            int f = tid + t * 256;            // 0..1535
            int arr = f >> 9, gg = f & 511;
            int row = gg >> 2, ch = gg & 3;
            uint32_t dst = base + (uint32_t)(arr * 2560 + row * 20 + ch * 4) * 4;
            const uint32_t* src =
                (arr == 0) ? Ahg + (size_t)(m0 + row) * KPAIRS + kp0 + ch * 4 :
                (arr == 1) ? Bhg + (size_t)(n0 + row) * KPAIRS + kp0 + ch * 4 :
                             Blg + (size_t)(n0 + row) * KPAIRS + kp0 + ch * 4;
            cp16(dst, src);
        }
    };

    load_tile(0, 0);
    CP_COMMIT();

    for (int kt = 0; kt < 32; kt++) {
        if (kt < 31) { load_tile(kt + 1, (kt + 1) & 1); CP_COMMIT(); CP_WAIT(1); }
        else         { CP_WAIT(0); }
        __syncthreads();

        const uint32_t base = SB + (uint32_t)(kt & 1) * 7680 * 4;
        const uint32_t AHB = base;
        const uint32_t BHB = base + 2560 * 4, BLB = base + 5120 * 4;

        #pragma unroll
        for (int s = 0; s < 2; s++) {
            uint32_t sc = s * 32;
            uint32_t ah0[4], ah1[4];
            ldsm_x4(ah0, AHB + a_off0 + sc);
            ldsm_x4(ah1, AHB + a_off1 + sc);
            #pragma unroll
            for (int hb = 0; hb < 2; hb++) {
                uint32_t boff = (hb ? b_off1 : b_off0) + sc;
                uint32_t bh0[4], bh1[4], bl0[4], bl1[4];
                ldsm_x4(bh0, BHB + boff);
                ldsm_x4(bh1, BHB + boff + 16);
                ldsm_x4(bl0, BLB + boff);
                ldsm_x4(bl1, BLB + boff + 16);
                #pragma unroll
                for (int j = 0; j < 4; j++) mma16(acc[0][hb*4+j], ah0, bh0[j], bh1[j]);
                #pragma unroll
                for (int j = 0; j < 4; j++) mma16(acc[1][hb*4+j], ah1, bh0[j], bh1[j]);
                #pragma unroll
                for (int j = 0; j < 4; j++) mma16(acc[0][hb*4+j], ah0, bl0[j], bl1[j]);
                #pragma unroll
                for (int j = 0; j < 4; j++) mma16(acc[1][hb*4+j], ah1, bl0[j], bl1[j]);
            }
        }
        __syncthreads();
    }

    #pragma unroll
    for (int mf = 0; mf < 2; mf++) {
        int mA = m0 + wm * 32 + mf * 16 + g;
        int mB = mA + 8;
        #pragma unroll
        for (int nf = 0; nf < 8; nf++) {
            float4 c = acc[mf][nf];
            int n = n0 + wn * 64 + nf * 8 + 2 * qd;
            *(float2*)(Outf + (size_t)mA * DMODEL + n) = make_float2(c.x, c.y);
            *(float2*)(Outf + (size_t)mB * DMODEL + n) = make_float2(c.z, c.w);
        }
    }
}

// ---------------------------------------------------------------------------
// Flash attention: S = QK^T 3-term; PV 2-term with P pure fp16 (no Pl).
// BQ=128 (8 warps x 16 rows), K tile 64, cp.async double-buffered, stride 36.
// ---------------------------------------------------------------------------
#define ATTN_SMEM ((9216 + 2 * 9216) * 4)   // 110592 B

__global__ __launch_bounds__(256, 2)
void attn_p()
{
    extern __shared__ uint32_t sa[];

    const int tid  = threadIdx.x;
    const int lane = tid & 31;
    const int g    = lane >> 2;
    const int qd   = lane & 3;
    const int wq0  = (tid >> 5) * 16;

    const int q0 = blockIdx.x * 128;
    const int h  = blockIdx.y;
    const int b  = blockIdx.z;
    const size_t base32 = ((size_t)h * BATCH + b) * SEQ * 32;

    const uint32_t SB = smem_u32(sa);
    const uint32_t QH = SB, QL = SB + 4608 * 4;

    const int arow = lane & 15, acol = (lane >> 4) * 4;
    const uint32_t q_off  = ((wq0 + arow) * 36 + acol) * 4;
    const uint32_t r_off0 = (lane * 36) * 4;
    const uint32_t r_off1 = r_off0 + 32 * 36 * 4;
    const uint32_t v_off = (((lane & 7) + ((lane >> 3) & 1) * 8) * 36
                            + (lane >> 4) * 4) * 4;

    auto load_q = [&]() {
        #pragma unroll
        for (int t = 0; t < 8; t++) {
            int f = tid + t * 256;
            int arr = f >> 10, gg = f & 1023;
            int row = gg >> 3, ch = gg & 7;
            uint32_t dst = SB + (uint32_t)((arr ? 4608 : 0) + row * 36 + ch * 4) * 4;
            const uint32_t* src = (arr ? g_Ql : g_Qh)
                + base32 + (size_t)(q0 + row) * 32 + ch * 4;
            cp16(dst, src);
        }
    };
    auto load_kv = [&](int kt, int bf) {
        uint32_t bb = SB + (uint32_t)(9216 + bf * 9216) * 4;
        int k0 = kt * 64;
        #pragma unroll
        for (int t = 0; t < 8; t++) {
            int f = tid + t * 256;
            int arr = f >> 9, gg = f & 511;
            int row = gg >> 3, ch = gg & 7;
            uint32_t dst = bb + (uint32_t)(arr * 2304 + row * 36 + ch * 4) * 4;
            const uint32_t* p =
                (arr == 0) ? g_Kh : (arr == 1) ? g_Kl : (arr == 2) ? g_Vh : g_Vl;
            cp16(dst, p + base32 + (size_t)(k0 + row) * 32 + ch * 4);
        }
    };

    load_q();
    load_kv(0, 0);
    CP_COMMIT();

    float4 o[8];
    #pragma unroll
    for (int j = 0; j < 8; j++) o[j] = make_float4(0.f, 0.f, 0.f, 0.f);
    float mA = -1e30f, mB = -1e30f, lA = 0.f, lB = 0.f;

    for (int kt = 0; kt < SEQ / 64; kt++) {
        if (kt < 31) { load_kv(kt + 1, (kt + 1) & 1); CP_COMMIT(); CP_WAIT(1); }
        else         { CP_WAIT(0); }
        __syncthreads();

        const uint32_t KB = SB + (uint32_t)(9216 + (kt & 1) * 9216) * 4;
        const uint32_t KH = KB, KL = KB + 2304 * 4;
        const uint32_t VH = KB + 4608 * 4, VL = KB + 6912 * 4;

        // ---- S = Q K^T (3-term)
        float4 s[8];
        #pragma unroll
        for (int j = 0; j < 8; j++) s[j] = make_float4(0.f, 0.f, 0.f, 0.f);

        #pragma unroll
        for (int st = 0; st < 4; st++) {
            uint32_t sc = st * 32;
            uint32_t ah[4], al[4];
            ldsm_x4(ah, QH + q_off + sc);
            ldsm_x4(al, QL + q_off + sc);
            #pragma unroll
            for (int hb = 0; hb < 2; hb++) {
                uint32_t boff = (hb ? r_off1 : r_off0) + sc;
                uint32_t bh0[4], bh1[4], bl0[4], bl1[4];
                ldsm_x4(bh0, KH + boff);
                ldsm_x4(bh1, KH + boff + 16);
                ldsm_x4(bl0, KL + boff);
                ldsm_x4(bl1, KL + boff + 16);
                #pragma unroll
                for (int j = 0; j < 4; j++) mma16(s[hb*4+j], ah, bh0[j], bh1[j]);
                #pragma unroll
                for (int j = 0; j < 4; j++) mma16(s[hb*4+j], ah, bl0[j], bl1[j]);
                #pragma unroll
                for (int j = 0; j < 4; j++) mma16(s[hb*4+j], al, bh0[j], bh1[j]);
            }
        }

        // ---- online softmax. (x,y): row g; (z,w): row g+8
        float mtA = -1e30f, mtB = -1e30f;
        #pragma unroll
        for (int nf = 0; nf < 8; nf++) {
            mtA = fmaxf(mtA, fmaxf(s[nf].x, s[nf].y));
            mtB = fmaxf(mtB, fmaxf(s[nf].z, s[nf].w));
        }
        mtA = fmaxf(mtA, __shfl_xor_sync(0xffffffffu, mtA, 1));
        mtA = fmaxf(mtA, __shfl_xor_sync(0xffffffffu, mtA, 2));
        mtB = fmaxf(mtB, __shfl_xor_sync(0xffffffffu, mtB, 1));
        mtB = fmaxf(mtB, __shfl_xor_sync(0xffffffffu, mtB, 2));

        float mnA = fmaxf(mA, mtA), mnB = fmaxf(mB, mtB);
        float alA = __expf(mA - mnA), alB = __expf(mB - mnB);
        float sumA = 0.f, sumB = 0.f;
        #pragma unroll
        for (int nf = 0; nf < 8; nf++) {
            s[nf].x = __expf(s[nf].x - mnA);
            s[nf].y = __expf(s[nf].y - mnA);
            s[nf].z = __expf(s[nf].z - mnB);
            s[nf].w = __expf(s[nf].w - mnB);
            sumA += s[nf].x + s[nf].y;
            sumB += s[nf].z + s[nf].w;
        }
        sumA += __shfl_xor_sync(0xffffffffu, sumA, 1);
        sumA += __shfl_xor_sync(0xffffffffu, sumA, 2);
        sumB += __shfl_xor_sync(0xffffffffu, sumB, 1);
        sumB += __shfl_xor_sync(0xffffffffu, sumB, 2);
        lA = lA * alA + sumA; mA = mnA;
        lB = lB * alB + sumB; mB = mnB;
        #pragma unroll
        for (int nf = 0; nf < 8; nf++) {
            o[nf].x *= alA; o[nf].y *= alA;
            o[nf].z *= alB; o[nf].w *= alB;
        }

        // ---- O += P V : P pure fp16 (2-term: Ph·Vh + Ph·Vl)
        #pragma unroll
        for (int st = 0; st < 4; st++) {
            uint32_t pah[4];
            pah[0] = pack2(s[2*st].x,   s[2*st].y);
            pah[1] = pack2(s[2*st].z,   s[2*st].w);
            pah[2] = pack2(s[2*st+1].x, s[2*st+1].y);
            pah[3] = pack2(s[2*st+1].z, s[2*st+1].w);
            uint32_t stoff = (uint32_t)(st * 16 * 36) * 4;
            #pragma unroll
            for (int egp = 0; egp < 2; egp++) {
                uint32_t e0 = (uint32_t)(egp * 2) * 32;
                uint32_t vh0[4], vh1[4], vl0[4], vl1[4];
                ldsm_x4t(vh0, VH + v_off + stoff + e0);
                ldsm_x4t(vh1, VH + v_off + stoff + e0 + 32);
                ldsm_x4t(vl0, VL + v_off + stoff + e0);
                ldsm_x4t(vl1, VL + v_off + stoff + e0 + 32);
                int nb = egp * 4;
                mma16(o[nb+0], pah, vh0[0], vh0[1]);
                mma16(o[nb+1], pah, vh0[2], vh0[3]);
                mma16(o[nb+2], pah, vh1[0], vh1[1]);
                mma16(o[nb+3], pah, vh1[2], vh1[3]);
                mma16(o[nb+0], pah, vl0[0], vl0[1]);
                mma16(o[nb+1], pah, vl0[2], vl0[3]);
                mma16(o[nb+2], pah, vl1[0], vl1[1]);
                mma16(o[nb+3], pah, vl1[2], vl1[3]);
            }
        }
        __syncthreads();
    }

    // Normalize; write hi-only H (lo path unused by 2-term out-proj, but keep
    // arrays consistent): store split pairs
    float invA = 1.f / lA, invB = 1.f / lB;
    int qA = q0 + wq0 + g, qB = qA + 8;
    #pragma unroll
    for (int nf = 0; nf < 8; nf++) {
        uint32_t hh, ll;
        int pr = h * 32 + nf * 4 + qd;
        split2(o[nf].x * invA, o[nf].y * invA, hh, ll);
        g_Hh[((size_t)b * SEQ + qA) * KPAIRS + pr] = hh;
        g_Hl[((size_t)b * SEQ + qA) * KPAIRS + pr] = ll;
        split2(o[nf].z * invB, o[nf].w * invB, hh, ll);
        g_Hh[((size_t)b * SEQ + qB) * KPAIRS + pr] = hh;
        g_Hl[((size_t)b * SEQ + qB) * KPAIRS + pr] = ll;
    }
}

// ---------------------------------------------------------------------------
extern "C" void kernel_launch(void* const* d_in, const int* in_sizes, int n_in,
                              void* d_out, int out_size)
{
    const float* q  = (const float*)d_in[0];
    const float* k  = (const float*)d_in[1];
    const float* v  = (const float*)d_in[2];
    const float* Wq = (const float*)d_in[3];
    const float* Wk = (const float*)d_in[4];
    const float* Wv = (const float*)d_in[5];
    const float* Wo = (const float*)d_in[6];
    float* out = (float*)d_out;

    cudaFuncSetAttribute(gemm_qkv, cudaFuncAttributeMaxDynamicSharedMemorySize, 81920);
    cudaFuncSetAttribute(gemm_out, cudaFuncAttributeMaxDynamicSharedMemorySize, 61440);
    cudaFuncSetAttribute(attn_p,   cudaFuncAttributeMaxDynamicSharedMemorySize, ATTN_SMEM);

    presplit_pairs3<<<dim3(NP / 256, 1, 3), 256>>>(q, k, v);
    presplit_wqkv3 <<<dim3(WN / 256, 1, 3), 256>>>(Wq, Wk, Wv);
    presplit_wo    <<<WN / 256, 256>>>(Wo);

    gemm_qkv<<<dim3(DMODEL / 128, MROWS / 128, 3), 256, 81920>>>();

    attn_p<<<dim3(SEQ / 128, NHEADS, BATCH), 256, ATTN_SMEM>>>();

    gemm_out<<<dim3(DMODEL / 128, MROWS / 128), 256, 61440>>>(out);
}

// round 10
// speedup vs baseline: 3.8619x; 1.2611x over previous
#include <cuda_runtime.h>
#include <cuda_fp16.h>
#include <stdint.h>

#define NHEADS 16
#define BATCH  2
#define SEQ    2048
#define DMODEL 1024
#define HID    64
#define MROWS  4096
#define KPAIRS 512          // DMODEL/2
#define NORM   0.125f
#define NP     (MROWS*KPAIRS)
#define WN     (DMODEL*KPAIRS)

// ---------------------------------------------------------------------------
// Global scratch. Inputs + Q + H are hi-only; K,V and weights are split.
// ---------------------------------------------------------------------------
__device__ uint32_t g_Xh[3u*NP];                  // inputs hi [which][m][kpair]
__device__ uint32_t g_Wh[4u*WN], g_Wl[4u*WN];     // weights hi/lo [which][n][kpair]
__device__ uint32_t g_Qh[NP];                     // [h][b][s][32 epairs] (hi only)
__device__ uint32_t g_Kh[NP], g_Kl[NP];
__device__ uint32_t g_Vh[NP], g_Vl[NP];
__device__ uint32_t g_Hh[NP];                     // attn out hi [b][s][512 pairs]

// ---------------------------------------------------------------------------
// helpers
// ---------------------------------------------------------------------------
__device__ __forceinline__ void split2(float x, float y, uint32_t& hi, uint32_t& lo) {
    __half hx = __float2half_rn(x), hy = __float2half_rn(y);
    __half2 H = __halves2half2(hx, hy);
    __half2 L = __floats2half2_rn(x - __half2float(hx), y - __half2float(hy));
    hi = *reinterpret_cast<uint32_t*>(&H);
    lo = *reinterpret_cast<uint32_t*>(&L);
}
__device__ __forceinline__ uint32_t pack2(float x, float y) {
    __half2 H = __floats2half2_rn(x, y);
    return *reinterpret_cast<uint32_t*>(&H);
}
__device__ __forceinline__ uint32_t smem_u32(const void* p) {
    return (uint32_t)__cvta_generic_to_shared(p);
}
__device__ __forceinline__ void ldsm_x4(uint32_t* r, uint32_t addr) {
    asm volatile("ldmatrix.sync.aligned.m8n8.x4.shared.b16 {%0,%1,%2,%3},[%4];"
        : "=r"(r[0]), "=r"(r[1]), "=r"(r[2]), "=r"(r[3]) : "r"(addr));
}
__device__ __forceinline__ void ldsm_x4t(uint32_t* r, uint32_t addr) {
    asm volatile("ldmatrix.sync.aligned.m8n8.x4.trans.shared.b16 {%0,%1,%2,%3},[%4];"
        : "=r"(r[0]), "=r"(r[1]), "=r"(r[2]), "=r"(r[3]) : "r"(addr));
}
__device__ __forceinline__ void mma16(float4& d, const uint32_t* a,
                                      uint32_t b0, uint32_t b1) {
    asm volatile(
        "mma.sync.aligned.m16n8k16.row.col.f32.f16.f16.f32 "
        "{%0,%1,%2,%3},{%4,%5,%6,%7},{%8,%9},{%0,%1,%2,%3};"
        : "+f"(d.x), "+f"(d.y), "+f"(d.z), "+f"(d.w)
        : "r"(a[0]), "r"(a[1]), "r"(a[2]), "r"(a[3]), "r"(b0), "r"(b1));
}
__device__ __forceinline__ void cp16(uint32_t dst, const void* src) {
    asm volatile("cp.async.cg.shared.global [%0], [%1], 16;" :: "r"(dst), "l"(src));
}
#define CP_COMMIT() asm volatile("cp.async.commit_group;")
#define CP_WAIT(N)  asm volatile("cp.async.wait_group %0;" :: "n"(N))

// ---------------------------------------------------------------------------
// presplit kernels
// ---------------------------------------------------------------------------
__global__ void presplit_hi3(const float* __restrict__ s0,
                             const float* __restrict__ s1,
                             const float* __restrict__ s2) {
    int z = blockIdx.z;
    const float* src = (z == 0) ? s0 : (z == 1) ? s1 : s2;
    int i = blockIdx.x * 256 + threadIdx.x;
    float2 v = ((const float2*)src)[i];
    g_Xh[(size_t)z * NP + i] = pack2(v.x, v.y);
}
__global__ void presplit_wqkv3(const float* __restrict__ W0,
                               const float* __restrict__ W1,
                               const float* __restrict__ W2) {
    int z = blockIdx.z;
    const float* W = (z == 0) ? W0 : (z == 1) ? W1 : W2;
    float scale = (z == 0) ? NORM : 1.0f;
    int i = blockIdx.x * 256 + threadIdx.x;
    int n = i >> 9, p = i & 511;
    int h = n >> 6, e = n & 63;
    const float* s = W + (size_t)h * DMODEL * HID + (size_t)(2 * p) * HID + e;
    uint32_t hh, ll; split2(s[0] * scale, s[HID] * scale, hh, ll);
    g_Wh[(size_t)z * WN + i] = hh;
    g_Wl[(size_t)z * WN + i] = ll;
}
__global__ void presplit_wo(const float* __restrict__ W) {
    int i = blockIdx.x * 256 + threadIdx.x;
    int n = i >> 9, p = i & 511;
    uint32_t hh, ll;
    split2(W[(size_t)(2 * p) * DMODEL + n], W[(size_t)(2 * p + 1) * DMODEL + n], hh, ll);
    g_Wh[3u * WN + i] = hh;
    g_Wl[3u * WN + i] = ll;
}

// ---------------------------------------------------------------------------
// QKV projection GEMM (merged z=0,1,2), 2-term: Ah·Bh + Ah·Bl (== Ah·B exact).
// BM=BN=128, BK=32 (16 pairs), 8 warps (4m x 2n). cp.async double-buffered.
// Smem/buffer: Ah/Bh/Bl [128][20] (stride 20 words, ldsm-conflict-free).
// ---------------------------------------------------------------------------
__global__ __launch_bounds__(256, 2)
void gemm_qkv()
{
    extern __shared__ uint32_t sg[];   // [2][3][2560]

    const int z    = blockIdx.z;
    const int tid  = threadIdx.x;
    const int lane = tid & 31;
    const int wid  = tid >> 5;
    const int g    = lane >> 2;
    const int qd   = lane & 3;
    const int wm   = wid >> 1;
    const int wn   = wid & 1;
    const int m0   = blockIdx.y * 128;
    const int n0   = blockIdx.x * 128;

    const uint32_t* Ahg = g_Xh + (size_t)z * NP;
    const uint32_t* Bhg = g_Wh + (size_t)z * WN;
    const uint32_t* Blg = g_Wl + (size_t)z * WN;

    const uint32_t SB = smem_u32(sg);
    const int arow = lane & 15, acol = (lane >> 4) * 4;
    const uint32_t a_off0 = ((wm * 32 + arow) * 20 + acol) * 4;
    const uint32_t a_off1 = a_off0 + 16 * 20 * 4;
    const uint32_t b_off0 = ((wn * 64 + lane) * 20) * 4;
    const uint32_t b_off1 = b_off0 + 32 * 20 * 4;

    float4 acc[2][8];
    #pragma unroll
    for (int i = 0; i < 2; i++)
        #pragma unroll
        for (int j = 0; j < 8; j++) acc[i][j] = make_float4(0.f, 0.f, 0.f, 0.f);

    auto load_tile = [&](int kt, int bf) {
        const uint32_t base = SB + (uint32_t)bf * 7680 * 4;
        int kp0 = kt * 16;
        #pragma unroll
        for (int t = 0; t < 6; t++) {
            int f = tid + t * 256;            // 0..1535
            int arr = f >> 9, gg = f & 511;
            int row = gg >> 2, ch = gg & 3;
            uint32_t dst = base + (uint32_t)(arr * 2560 + row * 20 + ch * 4) * 4;
            const uint32_t* src =
                (arr == 0) ? Ahg + (size_t)(m0 + row) * KPAIRS + kp0 + ch * 4 :
                (arr == 1) ? Bhg + (size_t)(n0 + row) * KPAIRS + kp0 + ch * 4 :
                             Blg + (size_t)(n0 + row) * KPAIRS + kp0 + ch * 4;
            cp16(dst, src);
        }
    };

    load_tile(0, 0);
    CP_COMMIT();

    for (int kt = 0; kt < 32; kt++) {
        if (kt < 31) { load_tile(kt + 1, (kt + 1) & 1); CP_COMMIT(); CP_WAIT(1); }
        else         { CP_WAIT(0); }
        __syncthreads();

        const uint32_t base = SB + (uint32_t)(kt & 1) * 7680 * 4;
        const uint32_t AHB = base;
        const uint32_t BHB = base + 2560 * 4, BLB = base + 5120 * 4;

        #pragma unroll
        for (int s = 0; s < 2; s++) {
            uint32_t sc = s * 32;
            uint32_t ah0[4], ah1[4];
            ldsm_x4(ah0, AHB + a_off0 + sc);
            ldsm_x4(ah1, AHB + a_off1 + sc);
            #pragma unroll
            for (int hb = 0; hb < 2; hb++) {
                uint32_t boff = (hb ? b_off1 : b_off0) + sc;
                uint32_t bh0[4], bh1[4], bl0[4], bl1[4];
                ldsm_x4(bh0, BHB + boff);
                ldsm_x4(bh1, BHB + boff + 16);
                ldsm_x4(bl0, BLB + boff);
                ldsm_x4(bl1, BLB + boff + 16);
                #pragma unroll
                for (int j = 0; j < 4; j++) mma16(acc[0][hb*4+j], ah0, bh0[j], bh1[j]);
                #pragma unroll
                for (int j = 0; j < 4; j++) mma16(acc[1][hb*4+j], ah1, bh0[j], bh1[j]);
                #pragma unroll
                for (int j = 0; j < 4; j++) mma16(acc[0][hb*4+j], ah0, bl0[j], bl1[j]);
                #pragma unroll
                for (int j = 0; j < 4; j++) mma16(acc[1][hb*4+j], ah1, bl0[j], bl1[j]);
            }
        }
        __syncthreads();
    }

    // Epilogue: Q hi-only; K,V split
    #pragma unroll
    for (int mf = 0; mf < 2; mf++) {
        int mA = m0 + wm * 32 + mf * 16 + g;
        int mB = mA + 8;
        #pragma unroll
        for (int nf = 0; nf < 8; nf++) {
            float4 c = acc[mf][nf];
            int head = (n0 >> 6) + wn;
            int pr   = nf * 4 + qd;
            int bA = mA >> 11, sA = mA & 2047;
            int bB = mB >> 11, sB = mB & 2047;
            size_t dA = (((size_t)head * BATCH + bA) * SEQ + sA) * 32 + pr;
            size_t dB = (((size_t)head * BATCH + bB) * SEQ + sB) * 32 + pr;
            if (z == 0) {
                g_Qh[dA] = pack2(c.x, c.y);
                g_Qh[dB] = pack2(c.z, c.w);
            } else {
                uint32_t* Oh = (z == 1) ? g_Kh : g_Vh;
                uint32_t* Ol = (z == 1) ? g_Kl : g_Vl;
                uint32_t hh, ll;
                split2(c.x, c.y, hh, ll);
                Oh[dA] = hh; Ol[dA] = ll;
                split2(c.z, c.w, hh, ll);
                Oh[dB] = hh; Ol[dB] = ll;
            }
        }
    }
}

// ---------------------------------------------------------------------------
// Output projection GEMM: 2-term (Ah·Bh + Ah·Bl), A = g_Hh (hi only).
// ---------------------------------------------------------------------------
__global__ __launch_bounds__(256, 2)
void gemm_out(float* __restrict__ Outf)
{
    extern __shared__ uint32_t sg[];   // [2][3][2560]

    const int tid  = threadIdx.x;
    const int lane = tid & 31;
    const int wid  = tid >> 5;
    const int g    = lane >> 2;
    const int qd   = lane & 3;
    const int wm   = wid >> 1;
    const int wn   = wid & 1;
    const int m0   = blockIdx.y * 128;
    const int n0   = blockIdx.x * 128;

    const uint32_t* Ahg = g_Hh;
    const uint32_t* Bhg = g_Wh + 3u * WN;
    const uint32_t* Blg = g_Wl + 3u * WN;

    const uint32_t SB = smem_u32(sg);
    const int arow = lane & 15, acol = (lane >> 4) * 4;
    const uint32_t a_off0 = ((wm * 32 + arow) * 20 + acol) * 4;
    const uint32_t a_off1 = a_off0 + 16 * 20 * 4;
    const uint32_t b_off0 = ((wn * 64 + lane) * 20) * 4;
    const uint32_t b_off1 = b_off0 + 32 * 20 * 4;

    float4 acc[2][8];
    #pragma unroll
    for (int i = 0; i < 2; i++)
        #pragma unroll
        for (int j = 0; j < 8; j++) acc[i][j] = make_float4(0.f, 0.f, 0.f, 0.f);

    auto load_tile = [&](int kt, int bf) {
        const uint32_t base = SB + (uint32_t)bf * 7680 * 4;
        int kp0 = kt * 16;
        #pragma unroll
        for (int t = 0; t < 6; t++) {
            int f = tid + t * 256;
            int arr = f >> 9, gg = f & 511;
            int row = gg >> 2, ch = gg & 3;
            uint32_t dst = base + (uint32_t)(arr * 2560 + row * 20 + ch * 4) * 4;
            const uint32_t* src =
                (arr == 0) ? Ahg + (size_t)(m0 + row) * KPAIRS + kp0 + ch * 4 :
                (arr == 1) ? Bhg + (size_t)(n0 + row) * KPAIRS + kp0 + ch * 4 :
                             Blg + (size_t)(n0 + row) * KPAIRS + kp0 + ch * 4;
            cp16(dst, src);
        }
    };

    load_tile(0, 0);
    CP_COMMIT();

    for (int kt = 0; kt < 32; kt++) {
        if (kt < 31) { load_tile(kt + 1, (kt + 1) & 1); CP_COMMIT(); CP_WAIT(1); }
        else         { CP_WAIT(0); }
        __syncthreads();

        const uint32_t base = SB + (uint32_t)(kt & 1) * 7680 * 4;
        const uint32_t AHB = base;
        const uint32_t BHB = base + 2560 * 4, BLB = base + 5120 * 4;

        #pragma unroll
        for (int s = 0; s < 2; s++) {
            uint32_t sc = s * 32;
            uint32_t ah0[4], ah1[4];
            ldsm_x4(ah0, AHB + a_off0 + sc);
            ldsm_x4(ah1, AHB + a_off1 + sc);
            #pragma unroll
            for (int hb = 0; hb < 2; hb++) {
                uint32_t boff = (hb ? b_off1 : b_off0) + sc;
                uint32_t bh0[4], bh1[4], bl0[4], bl1[4];
                ldsm_x4(bh0, BHB + boff);
                ldsm_x4(bh1, BHB + boff + 16);
                ldsm_x4(bl0, BLB + boff);
                ldsm_x4(bl1, BLB + boff + 16);
                #pragma unroll
                for (int j = 0; j < 4; j++) mma16(acc[0][hb*4+j], ah0, bh0[j], bh1[j]);
                #pragma unroll
                for (int j = 0; j < 4; j++) mma16(acc[1][hb*4+j], ah1, bh0[j], bh1[j]);
                #pragma unroll
                for (int j = 0; j < 4; j++) mma16(acc[0][hb*4+j], ah0, bl0[j], bl1[j]);
                #pragma unroll
                for (int j = 0; j < 4; j++) mma16(acc[1][hb*4+j], ah1, bl0[j], bl1[j]);
            }
        }
        __syncthreads();
    }

    #pragma unroll
    for (int mf = 0; mf < 2; mf++) {
        int mA = m0 + wm * 32 + mf * 16 + g;
        int mB = mA + 8;
        #pragma unroll
        for (int nf = 0; nf < 8; nf++) {
            float4 c = acc[mf][nf];
            int n = n0 + wn * 64 + nf * 8 + 2 * qd;
            *(float2*)(Outf + (size_t)mA * DMODEL + n) = make_float2(c.x, c.y);
            *(float2*)(Outf + (size_t)mB * DMODEL + n) = make_float2(c.z, c.w);
        }
    }
}

// ---------------------------------------------------------------------------
// Flash attention: S = Qh·(Kh+Kl) 2-term; PV 2-term (Ph·Vh + Ph·Vl).
// BQ=128 (8 warps x 16 rows), K tile 64, cp.async double-buffered, stride 36.
// Smem (words): Qh @0 (4608) | buf b @4608+b*9216: Kh,Kl,Vh,Vl (2304 each)
// ---------------------------------------------------------------------------
#define ATTN_SMEM ((4608 + 2 * 9216) * 4)   // 92160 B

__global__ __launch_bounds__(256, 2)
void attn_p()
{
    extern __shared__ uint32_t sa[];

    const int tid  = threadIdx.x;
    const int lane = tid & 31;
    const int g    = lane >> 2;
    const int qd   = lane & 3;
    const int wq0  = (tid >> 5) * 16;

    const int q0 = blockIdx.x * 128;
    const int h  = blockIdx.y;
    const int b  = blockIdx.z;
    const size_t base32 = ((size_t)h * BATCH + b) * SEQ * 32;

    const uint32_t SB = smem_u32(sa);
    const uint32_t QH = SB;

    const int arow = lane & 15, acol = (lane >> 4) * 4;
    const uint32_t q_off  = ((wq0 + arow) * 36 + acol) * 4;
    const uint32_t r_off0 = (lane * 36) * 4;
    const uint32_t r_off1 = r_off0 + 32 * 36 * 4;
    const uint32_t v_off = (((lane & 7) + ((lane >> 3) & 1) * 8) * 36
                            + (lane >> 4) * 4) * 4;

    auto load_q = [&]() {
        #pragma unroll
        for (int t = 0; t < 4; t++) {
            int f = tid + t * 256;              // 0..1023
            int row = f >> 3, ch = f & 7;
            uint32_t dst = SB + (uint32_t)(row * 36 + ch * 4) * 4;
            cp16(dst, g_Qh + base32 + (size_t)(q0 + row) * 32 + ch * 4);
        }
    };
    auto load_kv = [&](int kt, int bf) {
        uint32_t bb = SB + (uint32_t)(4608 + bf * 9216) * 4;
        int k0 = kt * 64;
        #pragma unroll
        for (int t = 0; t < 8; t++) {
            int f = tid + t * 256;
            int arr = f >> 9, gg = f & 511;
            int row = gg >> 3, ch = gg & 7;
            uint32_t dst = bb + (uint32_t)(arr * 2304 + row * 36 + ch * 4) * 4;
            const uint32_t* p =
                (arr == 0) ? g_Kh : (arr == 1) ? g_Kl : (arr == 2) ? g_Vh : g_Vl;
            cp16(dst, p + base32 + (size_t)(k0 + row) * 32 + ch * 4);
        }
    };

    load_q();
    load_kv(0, 0);
    CP_COMMIT();

    float4 o[8];
    #pragma unroll
    for (int j = 0; j < 8; j++) o[j] = make_float4(0.f, 0.f, 0.f, 0.f);
    float mA = -1e30f, mB = -1e30f, lA = 0.f, lB = 0.f;

    for (int kt = 0; kt < SEQ / 64; kt++) {
        if (kt < 31) { load_kv(kt + 1, (kt + 1) & 1); CP_COMMIT(); CP_WAIT(1); }
        else         { CP_WAIT(0); }
        __syncthreads();

        const uint32_t KB = SB + (uint32_t)(4608 + (kt & 1) * 9216) * 4;
        const uint32_t KH = KB, KL = KB + 2304 * 4;
        const uint32_t VH = KB + 4608 * 4, VL = KB + 6912 * 4;

        // ---- S = Qh K^T (2-term: Qh·Kh + Qh·Kl)
        float4 s[8];
        #pragma unroll
        for (int j = 0; j < 8; j++) s[j] = make_float4(0.f, 0.f, 0.f, 0.f);

        #pragma unroll
        for (int st = 0; st < 4; st++) {
            uint32_t sc = st * 32;
            uint32_t ah[4];
            ldsm_x4(ah, QH + q_off + sc);
            #pragma unroll
            for (int hb = 0; hb < 2; hb++) {
                uint32_t boff = (hb ? r_off1 : r_off0) + sc;
                uint32_t bh0[4], bh1[4], bl0[4], bl1[4];
                ldsm_x4(bh0, KH + boff);
                ldsm_x4(bh1, KH + boff + 16);
                ldsm_x4(bl0, KL + boff);
                ldsm_x4(bl1, KL + boff + 16);
                #pragma unroll
                for (int j = 0; j < 4; j++) mma16(s[hb*4+j], ah, bh0[j], bh1[j]);
                #pragma unroll
                for (int j = 0; j < 4; j++) mma16(s[hb*4+j], ah, bl0[j], bl1[j]);
            }
        }

        // ---- online softmax. (x,y): row g; (z,w): row g+8
        float mtA = -1e30f, mtB = -1e30f;
        #pragma unroll
        for (int nf = 0; nf < 8; nf++) {
            mtA = fmaxf(mtA, fmaxf(s[nf].x, s[nf].y));
            mtB = fmaxf(mtB, fmaxf(s[nf].z, s[nf].w));
        }
        mtA = fmaxf(mtA, __shfl_xor_sync(0xffffffffu, mtA, 1));
        mtA = fmaxf(mtA, __shfl_xor_sync(0xffffffffu, mtA, 2));
        mtB = fmaxf(mtB, __shfl_xor_sync(0xffffffffu, mtB, 1));
        mtB = fmaxf(mtB, __shfl_xor_sync(0xffffffffu, mtB, 2));

        float mnA = fmaxf(mA, mtA), mnB = fmaxf(mB, mtB);
        float alA = __expf(mA - mnA), alB = __expf(mB - mnB);
        float sumA = 0.f, sumB = 0.f;
        #pragma unroll
        for (int nf = 0; nf < 8; nf++) {
            s[nf].x = __expf(s[nf].x - mnA);
            s[nf].y = __expf(s[nf].y - mnA);
            s[nf].z = __expf(s[nf].z - mnB);
            s[nf].w = __expf(s[nf].w - mnB);
            sumA += s[nf].x + s[nf].y;
            sumB += s[nf].z + s[nf].w;
        }
        sumA += __shfl_xor_sync(0xffffffffu, sumA, 1);
        sumA += __shfl_xor_sync(0xffffffffu, sumA, 2);
        sumB += __shfl_xor_sync(0xffffffffu, sumB, 1);
        sumB += __shfl_xor_sync(0xffffffffu, sumB, 2);
        lA = lA * alA + sumA; mA = mnA;
        lB = lB * alB + sumB; mB = mnB;
        #pragma unroll
        for (int nf = 0; nf < 8; nf++) {
            o[nf].x *= alA; o[nf].y *= alA;
            o[nf].z *= alB; o[nf].w *= alB;
        }

        // ---- O += P V : P pure fp16 (2-term: Ph·Vh + Ph·Vl)
        #pragma unroll
        for (int st = 0; st < 4; st++) {
            uint32_t pah[4];
            pah[0] = pack2(s[2*st].x,   s[2*st].y);
            pah[1] = pack2(s[2*st].z,   s[2*st].w);
            pah[2] = pack2(s[2*st+1].x, s[2*st+1].y);
            pah[3] = pack2(s[2*st+1].z, s[2*st+1].w);
            uint32_t stoff = (uint32_t)(st * 16 * 36) * 4;
            #pragma unroll
            for (int egp = 0; egp < 2; egp++) {
                uint32_t e0 = (uint32_t)(egp * 2) * 32;
                uint32_t vh0[4], vh1[4], vl0[4], vl1[4];
                ldsm_x4t(vh0, VH + v_off + stoff + e0);
                ldsm_x4t(vh1, VH + v_off + stoff + e0 + 32);
                ldsm_x4t(vl0, VL + v_off + stoff + e0);
                ldsm_x4t(vl1, VL + v_off + stoff + e0 + 32);
                int nb = egp * 4;
                mma16(o[nb+0], pah, vh0[0], vh0[1]);
                mma16(o[nb+1], pah, vh0[2], vh0[3]);
                mma16(o[nb+2], pah, vh1[0], vh1[1]);
                mma16(o[nb+3], pah, vh1[2], vh1[3]);
                mma16(o[nb+0], pah, vl0[0], vl0[1]);
                mma16(o[nb+1], pah, vl0[2], vl0[3]);
                mma16(o[nb+2], pah, vl1[0], vl1[1]);
                mma16(o[nb+3], pah, vl1[2], vl1[3]);
            }
        }
        __syncthreads();
    }

    // Normalize; write hi-only H
    float invA = 1.f / lA, invB = 1.f / lB;
    int qA = q0 + wq0 + g, qB = qA + 8;
    #pragma unroll
    for (int nf = 0; nf < 8; nf++) {
        int pr = h * 32 + nf * 4 + qd;
        g_Hh[((size_t)b * SEQ + qA) * KPAIRS + pr] =
            pack2(o[nf].x * invA, o[nf].y * invA);
        g_Hh[((size_t)b * SEQ + qB) * KPAIRS + pr] =
            pack2(o[nf].z * invB, o[nf].w * invB);
    }
}

// ---------------------------------------------------------------------------
extern "C" void kernel_launch(void* const* d_in, const int* in_sizes, int n_in,
                              void* d_out, int out_size)
{
    const float* q  = (const float*)d_in[0];
    const float* k  = (const float*)d_in[1];
    const float* v  = (const float*)d_in[2];
    const float* Wq = (const float*)d_in[3];
    const float* Wk = (const float*)d_in[4];
    const float* Wv = (const float*)d_in[5];
    const float* Wo = (const float*)d_in[6];
    float* out = (float*)d_out;

    cudaFuncSetAttribute(gemm_qkv, cudaFuncAttributeMaxDynamicSharedMemorySize, 61440);
    cudaFuncSetAttribute(gemm_out, cudaFuncAttributeMaxDynamicSharedMemorySize, 61440);
    cudaFuncSetAttribute(attn_p,   cudaFuncAttributeMaxDynamicSharedMemorySize, ATTN_SMEM);

    presplit_hi3  <<<dim3(NP / 256, 1, 3), 256>>>(q, k, v);
    presplit_wqkv3<<<dim3(WN / 256, 1, 3), 256>>>(Wq, Wk, Wv);
    presplit_wo   <<<WN / 256, 256>>>(Wo);

    gemm_qkv<<<dim3(DMODEL / 128, MROWS / 128, 3), 256, 61440>>>();

    attn_p<<<dim3(SEQ / 128, NHEADS, BATCH), 256, ATTN_SMEM>>>();

    gemm_out<<<dim3(DMODEL / 128, MROWS / 128), 256, 61440>>>(out);
}

// round 11
// speedup vs baseline: 4.0751x; 1.0552x over previous
#include <cuda_runtime.h>
#include <cuda_fp16.h>
#include <stdint.h>

#define NHEADS 16
#define BATCH  2
#define SEQ    2048
#define DMODEL 1024
#define HID    64
#define MROWS  4096
#define KPAIRS 512          // DMODEL/2
#define NORM   0.125f
#define NP     (MROWS*KPAIRS)
#define WN     (DMODEL*KPAIRS)

// ---------------------------------------------------------------------------
// Global scratch. Inputs + Q + H are hi-only; K,V and weights are split.
// ---------------------------------------------------------------------------
__device__ uint32_t g_Xh[3u*NP];                  // inputs hi [which][m][kpair]
__device__ uint32_t g_Wh[4u*WN], g_Wl[4u*WN];     // weights hi/lo [which][n][kpair]
__device__ uint32_t g_Qh[NP];                     // [h][b][s][32 epairs] (hi only)
__device__ uint32_t g_Kh[NP], g_Kl[NP];
__device__ uint32_t g_Vh[NP], g_Vl[NP];
__device__ uint32_t g_Hh[NP];                     // attn out hi [b][s][512 pairs]

// ---------------------------------------------------------------------------
// helpers
// ---------------------------------------------------------------------------
__device__ __forceinline__ void split2(float x, float y, uint32_t& hi, uint32_t& lo) {
    __half hx = __float2half_rn(x), hy = __float2half_rn(y);
    __half2 H = __halves2half2(hx, hy);
    __half2 L = __floats2half2_rn(x - __half2float(hx), y - __half2float(hy));
    hi = *reinterpret_cast<uint32_t*>(&H);
    lo = *reinterpret_cast<uint32_t*>(&L);
}
__device__ __forceinline__ uint32_t pack2(float x, float y) {
    __half2 H = __floats2half2_rn(x, y);
    return *reinterpret_cast<uint32_t*>(&H);
}
__device__ __forceinline__ uint32_t smem_u32(const void* p) {
    return (uint32_t)__cvta_generic_to_shared(p);
}
__device__ __forceinline__ void ldsm_x4(uint32_t* r, uint32_t addr) {
    asm volatile("ldmatrix.sync.aligned.m8n8.x4.shared.b16 {%0,%1,%2,%3},[%4];"
        : "=r"(r[0]), "=r"(r[1]), "=r"(r[2]), "=r"(r[3]) : "r"(addr));
}
__device__ __forceinline__ void ldsm_x4t(uint32_t* r, uint32_t addr) {
    asm volatile("ldmatrix.sync.aligned.m8n8.x4.trans.shared.b16 {%0,%1,%2,%3},[%4];"
        : "=r"(r[0]), "=r"(r[1]), "=r"(r[2]), "=r"(r[3]) : "r"(addr));
}
__device__ __forceinline__ void mma16(float4& d, const uint32_t* a,
                                      uint32_t b0, uint32_t b1) {
    asm volatile(
        "mma.sync.aligned.m16n8k16.row.col.f32.f16.f16.f32 "
        "{%0,%1,%2,%3},{%4,%5,%6,%7},{%8,%9},{%0,%1,%2,%3};"
        : "+f"(d.x), "+f"(d.y), "+f"(d.z), "+f"(d.w)
        : "r"(a[0]), "r"(a[1]), "r"(a[2]), "r"(a[3]), "r"(b0), "r"(b1));
}
__device__ __forceinline__ void cp16(uint32_t dst, const void* src) {
    asm volatile("cp.async.cg.shared.global [%0], [%1], 16;" :: "r"(dst), "l"(src));
}
#define CP_COMMIT() asm volatile("cp.async.commit_group;")
#define CP_WAIT(N)  asm volatile("cp.async.wait_group %0;" :: "n"(N))

// ---------------------------------------------------------------------------
// presplit kernels
// ---------------------------------------------------------------------------
__global__ void presplit_hi3(const float* __restrict__ s0,
                             const float* __restrict__ s1,
                             const float* __restrict__ s2) {
    int z = blockIdx.z;
    const float* src = (z == 0) ? s0 : (z == 1) ? s1 : s2;
    int i = blockIdx.x * 256 + threadIdx.x;
    float2 v = ((const float2*)src)[i];
    g_Xh[(size_t)z * NP + i] = pack2(v.x, v.y);
}
__global__ void presplit_wqkv3(const float* __restrict__ W0,
                               const float* __restrict__ W1,
                               const float* __restrict__ W2) {
    int z = blockIdx.z;
    const float* W = (z == 0) ? W0 : (z == 1) ? W1 : W2;
    float scale = (z == 0) ? NORM : 1.0f;
    int i = blockIdx.x * 256 + threadIdx.x;
    int n = i >> 9, p = i & 511;
    int h = n >> 6, e = n & 63;
    const float* s = W + (size_t)h * DMODEL * HID + (size_t)(2 * p) * HID + e;
    uint32_t hh, ll; split2(s[0] * scale, s[HID] * scale, hh, ll);
    g_Wh[(size_t)z * WN + i] = hh;
    g_Wl[(size_t)z * WN + i] = ll;
}
__global__ void presplit_wo(const float* __restrict__ W) {
    int i = blockIdx.x * 256 + threadIdx.x;
    int n = i >> 9, p = i & 511;
    uint32_t hh, ll;
    split2(W[(size_t)(2 * p) * DMODEL + n], W[(size_t)(2 * p + 1) * DMODEL + n], hh, ll);
    g_Wh[3u * WN + i] = hh;
    g_Wl[3u * WN + i] = ll;
}

// ---------------------------------------------------------------------------
// QKV projection GEMM (merged z=0,1,2), 2-term: Ah·Bh + Ah·Bl (== Ah·B exact).
// BM=BN=128, BK=64 (32 pairs), 8 warps (4m x 2n). cp.async double-buffered.
// Smem/buffer: Ah/Bh/Bl [128][36] (stride 36 words, ldsm-conflict-free).
// Accumulation order per accumulator is IDENTICAL to the BK=32 version
// (k16 blocks ascend 0..63, same term order) -> bitwise-identical results.
// ---------------------------------------------------------------------------
#define GEMM_SMEM (2 * 3 * 4608 * 4)   // 110592 B

__global__ __launch_bounds__(256, 2)
void gemm_qkv()
{
    extern __shared__ uint32_t sg[];   // [2][3][4608]

    const int z    = blockIdx.z;
    const int tid  = threadIdx.x;
    const int lane = tid & 31;
    const int wid  = tid >> 5;
    const int g    = lane >> 2;
    const int qd   = lane & 3;
    const int wm   = wid >> 1;
    const int wn   = wid & 1;
    const int m0   = blockIdx.y * 128;
    const int n0   = blockIdx.x * 128;

    const uint32_t* Ahg = g_Xh + (size_t)z * NP;
    const uint32_t* Bhg = g_Wh + (size_t)z * WN;
    const uint32_t* Blg = g_Wl + (size_t)z * WN;

    const uint32_t SB = smem_u32(sg);
    const int arow = lane & 15, acol = (lane >> 4) * 4;
    const uint32_t a_off0 = ((wm * 32 + arow) * 36 + acol) * 4;
    const uint32_t a_off1 = a_off0 + 16 * 36 * 4;
    const uint32_t b_off0 = ((wn * 64 + lane) * 36) * 4;
    const uint32_t b_off1 = b_off0 + 32 * 36 * 4;

    float4 acc[2][8];
    #pragma unroll
    for (int i = 0; i < 2; i++)
        #pragma unroll
        for (int j = 0; j < 8; j++) acc[i][j] = make_float4(0.f, 0.f, 0.f, 0.f);

    auto load_tile = [&](int kt, int bf) {
        const uint32_t base = SB + (uint32_t)bf * 13824 * 4;
        int kp0 = kt * 32;
        #pragma unroll
        for (int t = 0; t < 12; t++) {
            int f = tid + t * 256;            // 0..3071
            int arr = f >> 10, gg = f & 1023;
            int row = gg >> 3, ch = gg & 7;
            uint32_t dst = base + (uint32_t)(arr * 4608 + row * 36 + ch * 4) * 4;
            const uint32_t* src =
                (arr == 0) ? Ahg + (size_t)(m0 + row) * KPAIRS + kp0 + ch * 4 :
                (arr == 1) ? Bhg + (size_t)(n0 + row) * KPAIRS + kp0 + ch * 4 :
                             Blg + (size_t)(n0 + row) * KPAIRS + kp0 + ch * 4;
            cp16(dst, src);
        }
    };

    load_tile(0, 0);
    CP_COMMIT();

    for (int kt = 0; kt < 16; kt++) {
        if (kt < 15) { load_tile(kt + 1, (kt + 1) & 1); CP_COMMIT(); CP_WAIT(1); }
        else         { CP_WAIT(0); }
        __syncthreads();

        const uint32_t base = SB + (uint32_t)(kt & 1) * 13824 * 4;
        const uint32_t AHB = base;
        const uint32_t BHB = base + 4608 * 4, BLB = base + 9216 * 4;

        #pragma unroll
        for (int s = 0; s < 4; s++) {
            uint32_t sc = s * 32;
            uint32_t ah0[4], ah1[4];
            ldsm_x4(ah0, AHB + a_off0 + sc);
            ldsm_x4(ah1, AHB + a_off1 + sc);
            #pragma unroll
            for (int hb = 0; hb < 2; hb++) {
                uint32_t boff = (hb ? b_off1 : b_off0) + sc;
                uint32_t bh0[4], bh1[4], bl0[4], bl1[4];
                ldsm_x4(bh0, BHB + boff);
                ldsm_x4(bh1, BHB + boff + 16);
                ldsm_x4(bl0, BLB + boff);
                ldsm_x4(bl1, BLB + boff + 16);
                #pragma unroll
                for (int j = 0; j < 4; j++) mma16(acc[0][hb*4+j], ah0, bh0[j], bh1[j]);
                #pragma unroll
                for (int j = 0; j < 4; j++) mma16(acc[1][hb*4+j], ah1, bh0[j], bh1[j]);
                #pragma unroll
                for (int j = 0; j < 4; j++) mma16(acc[0][hb*4+j], ah0, bl0[j], bl1[j]);
                #pragma unroll
                for (int j = 0; j < 4; j++) mma16(acc[1][hb*4+j], ah1, bl0[j], bl1[j]);
            }
        }
        __syncthreads();
    }

    // Epilogue: Q hi-only; K,V split
    #pragma unroll
    for (int mf = 0; mf < 2; mf++) {
        int mA = m0 + wm * 32 + mf * 16 + g;
        int mB = mA + 8;
        #pragma unroll
        for (int nf = 0; nf < 8; nf++) {
            float4 c = acc[mf][nf];
            int head = (n0 >> 6) + wn;
            int pr   = nf * 4 + qd;
            int bA = mA >> 11, sA = mA & 2047;
            int bB = mB >> 11, sB = mB & 2047;
            size_t dA = (((size_t)head * BATCH + bA) * SEQ + sA) * 32 + pr;
            size_t dB = (((size_t)head * BATCH + bB) * SEQ + sB) * 32 + pr;
            if (z == 0) {
                g_Qh[dA] = pack2(c.x, c.y);
                g_Qh[dB] = pack2(c.z, c.w);
            } else {
                uint32_t* Oh = (z == 1) ? g_Kh : g_Vh;
                uint32_t* Ol = (z == 1) ? g_Kl : g_Vl;
                uint32_t hh, ll;
                split2(c.x, c.y, hh, ll);
                Oh[dA] = hh; Ol[dA] = ll;
                split2(c.z, c.w, hh, ll);
                Oh[dB] = hh; Ol[dB] = ll;
            }
        }
    }
}

// ---------------------------------------------------------------------------
// Output projection GEMM: 2-term (Ah·Bh + Ah·Bl), A = g_Hh (hi only). BK=64.
// ---------------------------------------------------------------------------
__global__ __launch_bounds__(256, 2)
void gemm_out(float* __restrict__ Outf)
{
    extern __shared__ uint32_t sg[];   // [2][3][4608]

    const int tid  = threadIdx.x;
    const int lane = tid & 31;
    const int wid  = tid >> 5;
    const int g    = lane >> 2;
    const int qd   = lane & 3;
    const int wm   = wid >> 1;
    const int wn   = wid & 1;
    const int m0   = blockIdx.y * 128;
    const int n0   = blockIdx.x * 128;

    const uint32_t* Ahg = g_Hh;
    const uint32_t* Bhg = g_Wh + 3u * WN;
    const uint32_t* Blg = g_Wl + 3u * WN;

    const uint32_t SB = smem_u32(sg);
    const int arow = lane & 15, acol = (lane >> 4) * 4;
    const uint32_t a_off0 = ((wm * 32 + arow) * 36 + acol) * 4;
    const uint32_t a_off1 = a_off0 + 16 * 36 * 4;
    const uint32_t b_off0 = ((wn * 64 + lane) * 36) * 4;
    const uint32_t b_off1 = b_off0 + 32 * 36 * 4;

    float4 acc[2][8];
    #pragma unroll
    for (int i = 0; i < 2; i++)
        #pragma unroll
        for (int j = 0; j < 8; j++) acc[i][j] = make_float4(0.f, 0.f, 0.f, 0.f);

    auto load_tile = [&](int kt, int bf) {
        const uint32_t base = SB + (uint32_t)bf * 13824 * 4;
        int kp0 = kt * 32;
        #pragma unroll
        for (int t = 0; t < 12; t++) {
            int f = tid + t * 256;
            int arr = f >> 10, gg = f & 1023;
            int row = gg >> 3, ch = gg & 7;
            uint32_t dst = base + (uint32_t)(arr * 4608 + row * 36 + ch * 4) * 4;
            const uint32_t* src =
                (arr == 0) ? Ahg + (size_t)(m0 + row) * KPAIRS + kp0 + ch * 4 :
                (arr == 1) ? Bhg + (size_t)(n0 + row) * KPAIRS + kp0 + ch * 4 :
                             Blg + (size_t)(n0 + row) * KPAIRS + kp0 + ch * 4;
            cp16(dst, src);
        }
    };

    load_tile(0, 0);
    CP_COMMIT();

    for (int kt = 0; kt < 16; kt++) {
        if (kt < 15) { load_tile(kt + 1, (kt + 1) & 1); CP_COMMIT(); CP_WAIT(1); }
        else         { CP_WAIT(0); }
        __syncthreads();

        const uint32_t base = SB + (uint32_t)(kt & 1) * 13824 * 4;
        const uint32_t AHB = base;
        const uint32_t BHB = base + 4608 * 4, BLB = base + 9216 * 4;

        #pragma unroll
        for (int s = 0; s < 4; s++) {
            uint32_t sc = s * 32;
            uint32_t ah0[4], ah1[4];
            ldsm_x4(ah0, AHB + a_off0 + sc);
            ldsm_x4(ah1, AHB + a_off1 + sc);
            #pragma unroll
            for (int hb = 0; hb < 2; hb++) {
                uint32_t boff = (hb ? b_off1 : b_off0) + sc;
                uint32_t bh0[4], bh1[4], bl0[4], bl1[4];
                ldsm_x4(bh0, BHB + boff);
                ldsm_x4(bh1, BHB + boff + 16);
                ldsm_x4(bl0, BLB + boff);
                ldsm_x4(bl1, BLB + boff + 16);
                #pragma unroll
                for (int j = 0; j < 4; j++) mma16(acc[0][hb*4+j], ah0, bh0[j], bh1[j]);
                #pragma unroll
                for (int j = 0; j < 4; j++) mma16(acc[1][hb*4+j], ah1, bh0[j], bh1[j]);
                #pragma unroll
                for (int j = 0; j < 4; j++) mma16(acc[0][hb*4+j], ah0, bl0[j], bl1[j]);
                #pragma unroll
                for (int j = 0; j < 4; j++) mma16(acc[1][hb*4+j], ah1, bl0[j], bl1[j]);
            }
        }
        __syncthreads();
    }

    #pragma unroll
    for (int mf = 0; mf < 2; mf++) {
        int mA = m0 + wm * 32 + mf * 16 + g;
        int mB = mA + 8;
        #pragma unroll
        for (int nf = 0; nf < 8; nf++) {
            float4 c = acc[mf][nf];
            int n = n0 + wn * 64 + nf * 8 + 2 * qd;
            *(float2*)(Outf + (size_t)mA * DMODEL + n) = make_float2(c.x, c.y);
            *(float2*)(Outf + (size_t)mB * DMODEL + n) = make_float2(c.z, c.w);
        }
    }
}

// ---------------------------------------------------------------------------
// Flash attention — UNCHANGED from R10 (bitwise-identical numerics).
// S = Qh·(Kh+Kl) 2-term; PV 2-term (Ph·Vh + Ph·Vl).
// ---------------------------------------------------------------------------
#define ATTN_SMEM ((4608 + 2 * 9216) * 4)   // 92160 B

__global__ __launch_bounds__(256, 2)
void attn_p()
{
    extern __shared__ uint32_t sa[];

    const int tid  = threadIdx.x;
    const int lane = tid & 31;
    const int g    = lane >> 2;
    const int qd   = lane & 3;
    const int wq0  = (tid >> 5) * 16;

    const int q0 = blockIdx.x * 128;
    const int h  = blockIdx.y;
    const int b  = blockIdx.z;
    const size_t base32 = ((size_t)h * BATCH + b) * SEQ * 32;

    const uint32_t SB = smem_u32(sa);
    const uint32_t QH = SB;

    const int arow = lane & 15, acol = (lane >> 4) * 4;
    const uint32_t q_off  = ((wq0 + arow) * 36 + acol) * 4;
    const uint32_t r_off0 = (lane * 36) * 4;
    const uint32_t r_off1 = r_off0 + 32 * 36 * 4;
    const uint32_t v_off = (((lane & 7) + ((lane >> 3) & 1) * 8) * 36
                            + (lane >> 4) * 4) * 4;

    auto load_q = [&]() {
        #pragma unroll
        for (int t = 0; t < 4; t++) {
            int f = tid + t * 256;
            int row = f >> 3, ch = f & 7;
            uint32_t dst = SB + (uint32_t)(row * 36 + ch * 4) * 4;
            cp16(dst, g_Qh + base32 + (size_t)(q0 + row) * 32 + ch * 4);
        }
    };
    auto load_kv = [&](int kt, int bf) {
        uint32_t bb = SB + (uint32_t)(4608 + bf * 9216) * 4;
        int k0 = kt * 64;
        #pragma unroll
        for (int t = 0; t < 8; t++) {
            int f = tid + t * 256;
            int arr = f >> 9, gg = f & 511;
            int row = gg >> 3, ch = gg & 7;
            uint32_t dst = bb + (uint32_t)(arr * 2304 + row * 36 + ch * 4) * 4;
            const uint32_t* p =
                (arr == 0) ? g_Kh : (arr == 1) ? g_Kl : (arr == 2) ? g_Vh : g_Vl;
            cp16(dst, p + base32 + (size_t)(k0 + row) * 32 + ch * 4);
        }
    };

    load_q();
    load_kv(0, 0);
    CP_COMMIT();

    float4 o[8];
    #pragma unroll
    for (int j = 0; j < 8; j++) o[j] = make_float4(0.f, 0.f, 0.f, 0.f);
    float mA = -1e30f, mB = -1e30f, lA = 0.f, lB = 0.f;

    for (int kt = 0; kt < SEQ / 64; kt++) {
        if (kt < 31) { load_kv(kt + 1, (kt + 1) & 1); CP_COMMIT(); CP_WAIT(1); }
        else         { CP_WAIT(0); }
        __syncthreads();

        const uint32_t KB = SB + (uint32_t)(4608 + (kt & 1) * 9216) * 4;
        const uint32_t KH = KB, KL = KB + 2304 * 4;
        const uint32_t VH = KB + 4608 * 4, VL = KB + 6912 * 4;

        float4 s[8];
        #pragma unroll
        for (int j = 0; j < 8; j++) s[j] = make_float4(0.f, 0.f, 0.f, 0.f);

        #pragma unroll
        for (int st = 0; st < 4; st++) {
            uint32_t sc = st * 32;
            uint32_t ah[4];
            ldsm_x4(ah, QH + q_off + sc);
            #pragma unroll
            for (int hb = 0; hb < 2; hb++) {
                uint32_t boff = (hb ? r_off1 : r_off0) + sc;
                uint32_t bh0[4], bh1[4], bl0[4], bl1[4];
                ldsm_x4(bh0, KH + boff);
                ldsm_x4(bh1, KH + boff + 16);
                ldsm_x4(bl0, KL + boff);
                ldsm_x4(bl1, KL + boff + 16);
                #pragma unroll
                for (int j = 0; j < 4; j++) mma16(s[hb*4+j], ah, bh0[j], bh1[j]);
                #pragma unroll
                for (int j = 0; j < 4; j++) mma16(s[hb*4+j], ah, bl0[j], bl1[j]);
            }
        }

        float mtA = -1e30f, mtB = -1e30f;
        #pragma unroll
        for (int nf = 0; nf < 8; nf++) {
            mtA = fmaxf(mtA, fmaxf(s[nf].x, s[nf].y));
            mtB = fmaxf(mtB, fmaxf(s[nf].z, s[nf].w));
        }
        mtA = fmaxf(mtA, __shfl_xor_sync(0xffffffffu, mtA, 1));
        mtA = fmaxf(mtA, __shfl_xor_sync(0xffffffffu, mtA, 2));
        mtB = fmaxf(mtB, __shfl_xor_sync(0xffffffffu, mtB, 1));
        mtB = fmaxf(mtB, __shfl_xor_sync(0xffffffffu, mtB, 2));

        float mnA = fmaxf(mA, mtA), mnB = fmaxf(mB, mtB);
        float alA = __expf(mA - mnA), alB = __expf(mB - mnB);
        float sumA = 0.f, sumB = 0.f;
        #pragma unroll
        for (int nf = 0; nf < 8; nf++) {
            s[nf].x = __expf(s[nf].x - mnA);
            s[nf].y = __expf(s[nf].y - mnA);
            s[nf].z = __expf(s[nf].z - mnB);
            s[nf].w = __expf(s[nf].w - mnB);
            sumA += s[nf].x + s[nf].y;
            sumB += s[nf].z + s[nf].w;
        }
        sumA += __shfl_xor_sync(0xffffffffu, sumA, 1);
        sumA += __shfl_xor_sync(0xffffffffu, sumA, 2);
        sumB += __shfl_xor_sync(0xffffffffu, sumB, 1);
        sumB += __shfl_xor_sync(0xffffffffu, sumB, 2);
        lA = lA * alA + sumA; mA = mnA;
        lB = lB * alB + sumB; mB = mnB;
        #pragma unroll
        for (int nf = 0; nf < 8; nf++) {
            o[nf].x *= alA; o[nf].y *= alA;
            o[nf].z *= alB; o[nf].w *= alB;
        }

        #pragma unroll
        for (int st = 0; st < 4; st++) {
            uint32_t pah[4];
            pah[0] = pack2(s[2*st].x,   s[2*st].y);
            pah[1] = pack2(s[2*st].z,   s[2*st].w);
            pah[2] = pack2(s[2*st+1].x, s[2*st+1].y);
            pah[3] = pack2(s[2*st+1].z, s[2*st+1].w);
            uint32_t stoff = (uint32_t)(st * 16 * 36) * 4;
            #pragma unroll
            for (int egp = 0; egp < 2; egp++) {
                uint32_t e0 = (uint32_t)(egp * 2) * 32;
                uint32_t vh0[4], vh1[4], vl0[4], vl1[4];
                ldsm_x4t(vh0, VH + v_off + stoff + e0);
                ldsm_x4t(vh1, VH + v_off + stoff + e0 + 32);
                ldsm_x4t(vl0, VL + v_off + stoff + e0);
                ldsm_x4t(vl1, VL + v_off + stoff + e0 + 32);
                int nb = egp * 4;
                mma16(o[nb+0], pah, vh0[0], vh0[1]);
                mma16(o[nb+1], pah, vh0[2], vh0[3]);
                mma16(o[nb+2], pah, vh1[0], vh1[1]);
                mma16(o[nb+3], pah, vh1[2], vh1[3]);
                mma16(o[nb+0], pah, vl0[0], vl0[1]);
                mma16(o[nb+1], pah, vl0[2], vl0[3]);
                mma16(o[nb+2], pah, vl1[0], vl1[1]);
                mma16(o[nb+3], pah, vl1[2], vl1[3]);
            }
        }
        __syncthreads();
    }

    float invA = 1.f / lA, invB = 1.f / lB;
    int qA = q0 + wq0 + g, qB = qA + 8;
    #pragma unroll
    for (int nf = 0; nf < 8; nf++) {
        int pr = h * 32 + nf * 4 + qd;
        g_Hh[((size_t)b * SEQ + qA) * KPAIRS + pr] =
            pack2(o[nf].x * invA, o[nf].y * invA);
        g_Hh[((size_t)b * SEQ + qB) * KPAIRS + pr] =
            pack2(o[nf].z * invB, o[nf].w * invB);
    }
}

// ---------------------------------------------------------------------------
extern "C" void kernel_launch(void* const* d_in, const int* in_sizes, int n_in,
                              void* d_out, int out_size)
{
    const float* q  = (const float*)d_in[0];
    const float* k  = (const float*)d_in[1];
    const float* v  = (const float*)d_in[2];
    const float* Wq = (const float*)d_in[3];
    const float* Wk = (const float*)d_in[4];
    const float* Wv = (const float*)d_in[5];
    const float* Wo = (const float*)d_in[6];
    float* out = (float*)d_out;

    cudaFuncSetAttribute(gemm_qkv, cudaFuncAttributeMaxDynamicSharedMemorySize, GEMM_SMEM);
    cudaFuncSetAttribute(gemm_out, cudaFuncAttributeMaxDynamicSharedMemorySize, GEMM_SMEM);
    cudaFuncSetAttribute(attn_p,   cudaFuncAttributeMaxDynamicSharedMemorySize, ATTN_SMEM);

    presplit_hi3  <<<dim3(NP / 256, 1, 3), 256>>>(q, k, v);
    presplit_wqkv3<<<dim3(WN / 256, 1, 3), 256>>>(Wq, Wk, Wv);
    presplit_wo   <<<WN / 256, 256>>>(Wo);

    gemm_qkv<<<dim3(DMODEL / 128, MROWS / 128, 3), 256, GEMM_SMEM>>>();

    attn_p<<<dim3(SEQ / 128, NHEADS, BATCH), 256, ATTN_SMEM>>>();

    gemm_out<<<dim3(DMODEL / 128, MROWS / 128), 256, GEMM_SMEM>>>(out);
}